// round 12
// baseline (speedup 1.0000x reference)
#include <cuda_runtime.h>
#include <cuda_fp16.h>
#include <math.h>
#include <stdint.h>

#define TOK   4096   // B*S tokens
#define DM    1024
#define HID   4096
#define SEQL  2048
#define NB    2
#define NH    16
#define DH    64

// ---------------- scratch (allocation-free: __device__ globals) ----------------
__device__ float g_x1[TOK * DM];                         // residual after attention
__device__ __align__(256) __half g_xnh[TOK * DM];        // LN output, fp16
__device__ __align__(256) __half g_qkv16[3 * TOK * DM];  // fused q|k|v (q pre-scaled)
__device__ __align__(256) __half g_attn16[TOK * DM];
__device__ __align__(256) __half g_hid16[TOK * HID];
// weights transposed to [N,K] fp16
__device__ __align__(256) __half g_wqkv16[3 * DM * DM];  // fused wq|wk|wv rows
__device__ __align__(256) __half g_wo16[DM * DM];
__device__ __align__(256) __half g_w116[DM * HID];
__device__ __align__(256) __half g_w216[HID * DM];

#define SC_LOG2E 0.1803368801111f   // 0.125 * log2(e), folded into Q

// ---------------- base-target PTX helpers ----------------
__device__ __forceinline__ uint32_t smem_u32(const void* p) {
    uint32_t a;
    asm("{ .reg .u64 t; cvta.to.shared.u64 t, %1; cvt.u32.u64 %0, t; }"
        : "=r"(a) : "l"(p));
    return a;
}
__device__ __forceinline__ void cpa16(uint32_t s, const void* g) {
    asm volatile("cp.async.cg.shared.global [%0], [%1], 16;" :: "r"(s), "l"(g));
}
#define CP_COMMIT() asm volatile("cp.async.commit_group;" ::: "memory")
#define CP_WAIT(n)  asm volatile("cp.async.wait_group %0;" :: "n"(n) : "memory")

__device__ __forceinline__ void ldm_x4(uint32_t* r, uint32_t addr) {
    asm volatile("ldmatrix.sync.aligned.m8n8.x4.shared.b16 {%0,%1,%2,%3}, [%4];"
                 : "=r"(r[0]), "=r"(r[1]), "=r"(r[2]), "=r"(r[3]) : "r"(addr));
}
__device__ __forceinline__ void ldm_x4_t(uint32_t* r, uint32_t addr) {
    asm volatile("ldmatrix.sync.aligned.m8n8.x4.trans.shared.b16 {%0,%1,%2,%3}, [%4];"
                 : "=r"(r[0]), "=r"(r[1]), "=r"(r[2]), "=r"(r[3]) : "r"(addr));
}
__device__ __forceinline__ void mma_f16(float* d, const uint32_t* a, const uint32_t* b) {
    asm volatile(
        "mma.sync.aligned.m16n8k16.row.col.f32.f16.f16.f32 "
        "{%0,%1,%2,%3}, {%4,%5,%6,%7}, {%8,%9}, {%0,%1,%2,%3};"
        : "+f"(d[0]), "+f"(d[1]), "+f"(d[2]), "+f"(d[3])
        : "r"(a[0]), "r"(a[1]), "r"(a[2]), "r"(a[3]), "r"(b[0]), "r"(b[1]));
}
__device__ __forceinline__ uint32_t packh2(float lo, float hi) {
    __half2 t = __floats2half2_rn(lo, hi);
    return *(uint32_t*)&t;
}

// ---------------- LayerNorm helper (128 threads per token) ----------------
__device__ __forceinline__ void ln_token(const float* __restrict__ xrow,
                                         const float* __restrict__ gamma,
                                         const float* __restrict__ beta,
                                         __half* __restrict__ orow,
                                         int sub, float* smred)
{
    const float4* xr = (const float4*)xrow;
    float4 v0 = xr[sub];
    float4 v1 = xr[sub + 128];
    float s  = v0.x + v0.y + v0.z + v0.w + v1.x + v1.y + v1.z + v1.w;
    float ss = v0.x*v0.x + v0.y*v0.y + v0.z*v0.z + v0.w*v0.w
             + v1.x*v1.x + v1.y*v1.y + v1.z*v1.z + v1.w*v1.w;
    #pragma unroll
    for (int o = 16; o; o >>= 1) {
        s  += __shfl_xor_sync(0xffffffffu, s,  o);
        ss += __shfl_xor_sync(0xffffffffu, ss, o);
    }
    int w = sub >> 5, ln = sub & 31;
    if (ln == 0) { smred[w] = s; smred[4 + w] = ss; }
    __syncthreads();
    s  = smred[0] + smred[1] + smred[2] + smred[3];
    ss = smred[4] + smred[5] + smred[6] + smred[7];
    float mu   = s * (1.0f / DM);
    float var  = ss * (1.0f / DM) - mu * mu;
    float rstd = rsqrtf(var + 1e-5f);

    const float4* gr = (const float4*)gamma;
    const float4* br = (const float4*)beta;
    #pragma unroll
    for (int u = 0; u < 2; u++) {
        int i = sub + u * 128;
        float4 xv = xr[i], gv = gr[i], bv = br[i];
        float rx = (xv.x - mu) * rstd * gv.x + bv.x;
        float ry = (xv.y - mu) * rstd * gv.y + bv.y;
        float rz = (xv.z - mu) * rstd * gv.z + bv.z;
        float rw = (xv.w - mu) * rstd * gv.w + bv.w;
        uint2 pk;
        pk.x = packh2(rx, ry);
        pk.y = packh2(rz, rw);
        *(uint2*)(orow + i * 4) = pk;
    }
}

// ---------------- standalone LN (for LN2) ----------------
__global__ void ln_kernel(const float* __restrict__ x,
                          const float* __restrict__ gamma,
                          const float* __restrict__ beta,
                          __half* __restrict__ out)
{
    __shared__ float smred[8];
    int t = blockIdx.x;
    ln_token(x + (size_t)t * DM, gamma, beta, out + (size_t)t * DM,
             threadIdx.x, smred);
}

// ------- fused prep: six weight transposes + LN1, one launch ------------------
// blocks [0,12288): weight tiles; blocks [12288,14336): LN1, 2 tokens each.
__global__ void wprep_kernel(const float* __restrict__ wq, const float* __restrict__ wk,
                             const float* __restrict__ wv, const float* __restrict__ wo,
                             const float* __restrict__ w1, const float* __restrict__ w2,
                             __half* __restrict__ owqkv, __half* __restrict__ owo,
                             __half* __restrict__ ow1,   __half* __restrict__ ow2,
                             const float* __restrict__ x,
                             const float* __restrict__ g1, const float* __restrict__ be1,
                             __half* __restrict__ oln)
{
    __shared__ float t[32][33];
    __shared__ float smred[2][8];
    int bid = blockIdx.x;
    int tx = threadIdx.x, ty = threadIdx.y;
    int tid = ty * 32 + tx;

    if (bid >= 12288) {
        int tok = (bid - 12288) * 2 + (tid >> 7);
        ln_token(x + (size_t)tok * DM, g1, be1, oln + (size_t)tok * DM,
                 tid & 127, smred[tid >> 7]);
        return;
    }

    const float* src; __half* dst; int K, N, tile;
    if (bid < 1024)      { src = wq; dst = owqkv;                 K = DM;  N = DM;  tile = bid; }
    else if (bid < 2048) { src = wk; dst = owqkv + DM * DM;       K = DM;  N = DM;  tile = bid - 1024; }
    else if (bid < 3072) { src = wv; dst = owqkv + 2 * DM * DM;   K = DM;  N = DM;  tile = bid - 2048; }
    else if (bid < 4096) { src = wo; dst = owo;                   K = DM;  N = DM;  tile = bid - 3072; }
    else if (bid < 8192) { src = w1; dst = ow1;                   K = DM;  N = HID; tile = bid - 4096; }
    else                 { src = w2; dst = ow2;                   K = HID; N = DM;  tile = bid - 8192; }
    int tpr = N >> 5;
    int n0 = (tile % tpr) * 32, k0 = (tile / tpr) * 32;

    #pragma unroll
    for (int i = 0; i < 4; i++)
        t[ty + i * 8][tx] = src[(size_t)(k0 + ty + i * 8) * N + n0 + tx];
    __syncthreads();
    #pragma unroll
    for (int i = 0; i < 4; i++)
        dst[(size_t)(n0 + ty + i * 8) * K + k0 + tx] = __float2half_rn(t[tx][ty + i * 8]);
}

// ---------------- mma.sync fp16 GEMM, 256x128 CTA tile, 4-stage ring ----------
#define GLDA      144
#define GA_BYTES  (256 * GLDA)             // 36864
#define GB_BYTES  (128 * GLDA)             // 18432
#define GSTAGE    (GA_BYTES + GB_BYTES)    // 55296
#define GEMM_SMEM (4 * GSTAGE)             // 221184

template<bool BIAS, bool RELU, bool RES, bool OUTH, bool QKVOUT>
__global__ void __launch_bounds__(256) tc_gemm_kernel(
    const __half* __restrict__ A, const __half* __restrict__ B,
    const float* __restrict__ bias, const float* __restrict__ Res,
    float* __restrict__ Cf, __half* __restrict__ Ch, int M, int N, int K)
{
    extern __shared__ char smem[];
    const uint32_t sb = smem_u32(smem);
    int tid = threadIdx.x;
    int wid = tid >> 5, lane = tid & 31;
    int wm = wid & 3, wn = wid >> 2;
    int m0 = blockIdx.y * 256, n0 = blockIdx.x * 128;

    float acc[4][8][4];
    #pragma unroll
    for (int i = 0; i < 4; i++)
        #pragma unroll
        for (int j = 0; j < 8; j++)
            #pragma unroll
            for (int r = 0; r < 4; r++) acc[i][j][r] = 0.f;

    int nc = K >> 6;

    auto load_chunk = [&](int c, int st) {
        int kc = c << 6;
        uint32_t base = sb + st * GSTAGE;
        #pragma unroll
        for (int i = 0; i < 12; i++) {
            int slot = tid + (i << 8);
            if (slot < 2048) {
                int r = slot >> 3, ch = slot & 7;
                cpa16(base + r * GLDA + ch * 16,
                      A + (size_t)(m0 + r) * K + kc + ch * 8);
            } else {
                int s2 = slot - 2048;
                int r = s2 >> 3, ch = s2 & 7;
                cpa16(base + GA_BYTES + r * GLDA + ch * 16,
                      B + (size_t)(n0 + r) * K + kc + ch * 8);
            }
        }
        CP_COMMIT();
    };

    load_chunk(0, 0);
    load_chunk(1, 1);
    load_chunk(2, 2);

    uint32_t aOff = (uint32_t)((wm * 64 + (lane & 15)) * GLDA + (lane >> 4) * 16);
    int bm = lane >> 3, brr = lane & 7;
    uint32_t bOff = (uint32_t)((wn * 64 + ((bm & 2) ? 8 : 0) + brr) * GLDA
                               + ((bm & 1) ? 16 : 0));

    for (int c = 0; c < nc; c++) {
        int st = c & 3;
        CP_WAIT(2);
        __syncthreads();
        if (c + 3 < nc) load_chunk(c + 3, (c + 3) & 3);
        else            CP_COMMIT();
        uint32_t base = sb + st * GSTAGE;
        #pragma unroll
        for (int ks = 0; ks < 4; ks++) {
            uint32_t kb = ks * 32;
            uint32_t af[4][4], bf[8][2];
            #pragma unroll
            for (int mt = 0; mt < 4; mt++)
                ldm_x4(af[mt], base + aOff + mt * (16 * GLDA) + kb);
            #pragma unroll
            for (int p = 0; p < 4; p++) {
                uint32_t t4[4];
                ldm_x4(t4, base + GA_BYTES + bOff + p * (16 * GLDA) + kb);
                bf[2*p][0] = t4[0]; bf[2*p][1] = t4[1];
                bf[2*p+1][0] = t4[2]; bf[2*p+1][1] = t4[3];
            }
            #pragma unroll
            for (int mt = 0; mt < 4; mt++)
                #pragma unroll
                for (int nt = 0; nt < 8; nt++)
                    mma_f16(acc[mt][nt], af[mt], bf[nt]);
        }
    }

    int g = lane >> 2, tq = lane & 3;
    #pragma unroll
    for (int mt = 0; mt < 4; mt++) {
        int mbase = m0 + wm * 64 + mt * 16 + g;
        #pragma unroll
        for (int nt = 0; nt < 8; nt++) {
            int n = n0 + wn * 64 + nt * 8 + tq * 2;
            float2 v0 = make_float2(acc[mt][nt][0], acc[mt][nt][1]);
            float2 v1 = make_float2(acc[mt][nt][2], acc[mt][nt][3]);
            if (BIAS) {
                float2 bb = *(const float2*)(bias + n);
                v0.x += bb.x; v0.y += bb.y; v1.x += bb.x; v1.y += bb.y;
            }
            if (RELU) {
                v0.x = fmaxf(v0.x, 0.f); v0.y = fmaxf(v0.y, 0.f);
                v1.x = fmaxf(v1.x, 0.f); v1.y = fmaxf(v1.y, 0.f);
            }
            if (RES) {
                float2 q0 = *(const float2*)(Res + (size_t)mbase * N + n);
                float2 q1 = *(const float2*)(Res + (size_t)(mbase + 8) * N + n);
                v0.x += q0.x; v0.y += q0.y; v1.x += q1.x; v1.y += q1.y;
            }
            if (QKVOUT) {
                int which = n >> 10, nn = n & 1023;
                if (which == 0) {
                    v0.x *= SC_LOG2E; v0.y *= SC_LOG2E;
                    v1.x *= SC_LOG2E; v1.y *= SC_LOG2E;
                }
                __half* dst = Ch + (size_t)which * (TOK * DM) + (size_t)mbase * DM + nn;
                *(uint32_t*)dst                    = packh2(v0.x, v0.y);
                *(uint32_t*)(dst + (size_t)8 * DM) = packh2(v1.x, v1.y);
            } else if (OUTH) {
                *(uint32_t*)(Ch + (size_t)mbase * N + n)       = packh2(v0.x, v0.y);
                *(uint32_t*)(Ch + (size_t)(mbase + 8) * N + n) = packh2(v1.x, v1.y);
            } else {
                *(float2*)(Cf + (size_t)mbase * N + n) = v0;
                *(float2*)(Cf + (size_t)(mbase + 8) * N + n) = v1;
            }
        }
    }
}

// ---------------- tensor-core flash attention (fp16, base-2 softmax) ----------
// 128 queries x (head, batch), 256 threads; 2 KV stages, 3 CTAs/SM target.
#define ALD  144
#define ATB  (64 * ALD)
#define QTB  (128 * ALD)
#define ASTG (2 * ATB)              // K, V per stage
#define ATT_SMEM (QTB + 2 * ASTG)   // 55296

__global__ void __launch_bounds__(256, 3) attn_tc_kernel(
    const __half* __restrict__ Q, const __half* __restrict__ K,
    const __half* __restrict__ V, __half* __restrict__ O)
{
    extern __shared__ char smc[];
    const uint32_t sb = smem_u32(smc);
    int qt = (int)gridDim.x - 1 - (int)blockIdx.x;
    int h = blockIdx.y, b = blockIdx.z;
    int tid = threadIdx.x;
    int wm = tid >> 5, lane = tid & 31;

    auto load_kv = [&](int t, int st) {
        uint32_t base = sb + QTB + st * ASTG;
        #pragma unroll
        for (int i = 0; i < 2; i++) {
            int slot = tid * 2 + i;
            int r = slot >> 3, c = slot & 7;
            size_t gk = (size_t)(b * SEQL + t * 64 + r) * DM + h * DH + c * 8;
            uint32_t so = (uint32_t)(r * ALD + c * 16);
            cpa16(base + so,       K + gk);
            cpa16(base + ATB + so, V + gk);
        }
        CP_COMMIT();
    };

    #pragma unroll
    for (int i = 0; i < 4; i++) {
        int slot = tid * 4 + i;
        int r = slot >> 3, c = slot & 7;
        size_t gq = (size_t)(b * SEQL + qt * 128 + r) * DM + h * DH + c * 8;
        cpa16(sb + (uint32_t)(r * ALD + c * 16), Q + gq);
    }
    load_kv(0, 0);

    float oacc[8][4];
    #pragma unroll
    for (int nt = 0; nt < 8; nt++)
        #pragma unroll
        for (int j = 0; j < 4; j++) oacc[nt][j] = 0.f;
    float mrow[2] = {-INFINITY, -INFINITY};
    float lrow[2] = {0.f, 0.f};

    uint32_t aOff = (uint32_t)((wm * 16 + (lane & 15)) * ALD + (lane >> 4) * 16);
    int bm = lane >> 3, brr = lane & 7;
    uint32_t bOff = (uint32_t)((((bm & 2) ? 8 : 0) + brr) * ALD + ((bm & 1) ? 16 : 0));
    uint32_t vtOff = (uint32_t)((lane & 15) * ALD + (lane >> 4) * 16);

    int ntile = 2 * qt + 2;
    for (int t = 0; t < ntile; t++) {
        int st = t & 1;
        CP_WAIT(0);
        __syncthreads();
        // prefetch into st^1 (consumed in iter t-1; all warps passed this barrier)
        if (t + 1 < ntile) load_kv(t + 1, st ^ 1);

        uint32_t kbase = sb + QTB + st * ASTG;
        uint32_t vbase = kbase + ATB;

        // ---- scores (pre-scaled Q -> already base-2) ----
        float sacc[8][4];
        #pragma unroll
        for (int nt = 0; nt < 8; nt++)
            #pragma unroll
            for (int j = 0; j < 4; j++) sacc[nt][j] = 0.f;

        #pragma unroll
        for (int kt = 0; kt < 4; kt++) {
            uint32_t kb = kt * 32;
            uint32_t a4[4];
            ldm_x4(a4, sb + aOff + kb);
            #pragma unroll
            for (int p = 0; p < 4; p++) {
                uint32_t t4[4];
                ldm_x4(t4, kbase + bOff + p * (16 * ALD) + kb);
                uint32_t b0[2] = {t4[0], t4[1]}, b1[2] = {t4[2], t4[3]};
                mma_f16(sacc[2*p],   a4, b0);
                mma_f16(sacc[2*p+1], a4, b1);
            }
        }

        // ---- causal mask only on diagonal tiles ----
        int g = lane >> 2, colb = (lane & 3) * 2;
        if (t >= 2 * qt) {
            #pragma unroll
            for (int nt = 0; nt < 8; nt++)
                #pragma unroll
                for (int j = 0; j < 4; j++) {
                    int col = t * 64 + nt * 8 + colb + (j & 1);
                    int qr  = qt * 128 + wm * 16 + g + ((j >= 2) ? 8 : 0);
                    if (col > qr) sacc[nt][j] = -1e30f;
                }
        }

        // ---- row max + rescale factors ----
        float mt0 = -INFINITY, mt1 = -INFINITY;
        #pragma unroll
        for (int nt = 0; nt < 8; nt++) {
            mt0 = fmaxf(mt0, fmaxf(sacc[nt][0], sacc[nt][1]));
            mt1 = fmaxf(mt1, fmaxf(sacc[nt][2], sacc[nt][3]));
        }
        mt0 = fmaxf(mt0, __shfl_xor_sync(0xffffffffu, mt0, 1));
        mt0 = fmaxf(mt0, __shfl_xor_sync(0xffffffffu, mt0, 2));
        mt1 = fmaxf(mt1, __shfl_xor_sync(0xffffffffu, mt1, 1));
        mt1 = fmaxf(mt1, __shfl_xor_sync(0xffffffffu, mt1, 2));
        float mn0 = fmaxf(mrow[0], mt0), mn1 = fmaxf(mrow[1], mt1);
        float sc0 = exp2f(mrow[0] - mn0), sc1 = exp2f(mrow[1] - mn1);
        mrow[0] = mn0; mrow[1] = mn1;
        #pragma unroll
        for (int nt = 0; nt < 8; nt++) {
            oacc[nt][0] *= sc0; oacc[nt][1] *= sc0;
            oacc[nt][2] *= sc1; oacc[nt][3] *= sc1;
        }

        // ---- interleaved exp2 + PV mma ----
        float lt0 = 0.f, lt1 = 0.f;
        #pragma unroll
        for (int kk = 0; kk < 4; kk++) {
            float p00 = exp2f(sacc[2*kk][0]   - mn0);
            float p01 = exp2f(sacc[2*kk][1]   - mn0);
            float p02 = exp2f(sacc[2*kk][2]   - mn1);
            float p03 = exp2f(sacc[2*kk][3]   - mn1);
            float p10 = exp2f(sacc[2*kk+1][0] - mn0);
            float p11 = exp2f(sacc[2*kk+1][1] - mn0);
            float p12 = exp2f(sacc[2*kk+1][2] - mn1);
            float p13 = exp2f(sacc[2*kk+1][3] - mn1);
            lt0 += (p00 + p01) + (p10 + p11);
            lt1 += (p02 + p03) + (p12 + p13);
            uint32_t pa[4];
            pa[0] = packh2(p00, p01);
            pa[1] = packh2(p02, p03);
            pa[2] = packh2(p10, p11);
            pa[3] = packh2(p12, p13);
            uint32_t rowb = vbase + vtOff + kk * (16 * ALD);
            #pragma unroll
            for (int p = 0; p < 4; p++) {
                uint32_t t4[4];
                ldm_x4_t(t4, rowb + p * 32);
                uint32_t b0[2] = {t4[0], t4[1]}, b1[2] = {t4[2], t4[3]};
                mma_f16(oacc[2*p],   pa, b0);
                mma_f16(oacc[2*p+1], pa, b1);
            }
        }
        lt0 += __shfl_xor_sync(0xffffffffu, lt0, 1);
        lt0 += __shfl_xor_sync(0xffffffffu, lt0, 2);
        lt1 += __shfl_xor_sync(0xffffffffu, lt1, 1);
        lt1 += __shfl_xor_sync(0xffffffffu, lt1, 2);
        lrow[0] = lrow[0] * sc0 + lt0;
        lrow[1] = lrow[1] * sc1 + lt1;
    }

    // ---- epilogue: fp16 out ----
    float inv0 = 1.0f / lrow[0], inv1 = 1.0f / lrow[1];
    int g = lane >> 2, tq = lane & 3;
    int row0 = qt * 128 + wm * 16 + g;
    #pragma unroll
    for (int nt = 0; nt < 8; nt++) {
        int d = h * DH + nt * 8 + tq * 2;
        *(uint32_t*)(O + (size_t)(b * SEQL + row0) * DM + d) =
            packh2(oacc[nt][0] * inv0, oacc[nt][1] * inv0);
        *(uint32_t*)(O + (size_t)(b * SEQL + row0 + 8) * DM + d) =
            packh2(oacc[nt][2] * inv1, oacc[nt][3] * inv1);
    }
}

// ---------------- launch ----------------
extern "C" void kernel_launch(void* const* d_in, const int* in_sizes, int n_in,
                              void* d_out, int out_size)
{
    const float* x   = (const float*)d_in[0];
    const float* wq  = (const float*)d_in[1];
    const float* wk  = (const float*)d_in[2];
    const float* wv  = (const float*)d_in[3];
    const float* wo  = (const float*)d_in[4];
    const float* w1  = (const float*)d_in[5];
    const float* b1  = (const float*)d_in[6];
    const float* w2  = (const float*)d_in[7];
    const float* b2  = (const float*)d_in[8];
    const float* g1  = (const float*)d_in[9];
    const float* be1 = (const float*)d_in[10];
    const float* g2  = (const float*)d_in[11];
    const float* be2 = (const float*)d_in[12];
    float* out = (float*)d_out;

    float* x1;
    cudaGetSymbolAddress((void**)&x1, g_x1);
    __half *xnh, *qkv16, *attn16, *hid16;
    __half *wqkv16, *wo16, *w116, *w216;
    cudaGetSymbolAddress((void**)&xnh,    g_xnh);
    cudaGetSymbolAddress((void**)&qkv16,  g_qkv16);
    cudaGetSymbolAddress((void**)&attn16, g_attn16);
    cudaGetSymbolAddress((void**)&hid16,  g_hid16);
    cudaGetSymbolAddress((void**)&wqkv16, g_wqkv16);
    cudaGetSymbolAddress((void**)&wo16,   g_wo16);
    cudaGetSymbolAddress((void**)&w116,   g_w116);
    cudaGetSymbolAddress((void**)&w216,   g_w216);
    __half* q16 = qkv16;
    __half* k16 = qkv16 + (size_t)TOK * DM;
    __half* v16 = qkv16 + 2 * (size_t)TOK * DM;

    cudaFuncSetAttribute(attn_tc_kernel, cudaFuncAttributeMaxDynamicSharedMemorySize,
                         ATT_SMEM);
    cudaFuncSetAttribute(tc_gemm_kernel<false, false, false, true, true>,
                         cudaFuncAttributeMaxDynamicSharedMemorySize, GEMM_SMEM);
    cudaFuncSetAttribute(tc_gemm_kernel<false, false, true, false, false>,
                         cudaFuncAttributeMaxDynamicSharedMemorySize, GEMM_SMEM);
    cudaFuncSetAttribute(tc_gemm_kernel<true, true, false, true, false>,
                         cudaFuncAttributeMaxDynamicSharedMemorySize, GEMM_SMEM);
    cudaFuncSetAttribute(tc_gemm_kernel<true, false, true, false, false>,
                         cudaFuncAttributeMaxDynamicSharedMemorySize, GEMM_SMEM);

    // fused weight prep + LN1 (single launch)
    wprep_kernel<<<14336, dim3(32, 8)>>>(wq, wk, wv, wo, w1, w2,
                                         wqkv16, wo16, w116, w216,
                                         x, g1, be1, xnh);

    // fused QKV projection (N=3072) -> q|k|v fp16 (q pre-scaled)
    tc_gemm_kernel<false, false, false, true, true>
        <<<dim3(3 * DM / 128, TOK / 256), 256, GEMM_SMEM>>>(
        xnh, wqkv16, nullptr, nullptr, nullptr, qkv16, TOK, 3 * DM, DM);

    // tensor-core attention -> fp16 (V consumed in natural layout)
    attn_tc_kernel<<<dim3(SEQL / 128, NH, NB), 256, ATT_SMEM>>>(q16, k16, v16, attn16);

    // O projection + residual(x) -> x1 (fp32)
    tc_gemm_kernel<false, false, true, false, false>
        <<<dim3(DM / 128, TOK / 256), 256, GEMM_SMEM>>>(
        attn16, wo16, nullptr, x, x1, nullptr, TOK, DM, DM);

    // LN2 -> fp16
    ln_kernel<<<TOK, 128>>>(x1, g2, be2, xnh);

    // FFN1: relu(xn @ w1 + b1) -> fp16 hid
    tc_gemm_kernel<true, true, false, true, false>
        <<<dim3(HID / 128, TOK / 256), 256, GEMM_SMEM>>>(
        xnh, w116, b1, nullptr, nullptr, hid16, TOK, HID, DM);

    // FFN2: hid @ w2 + b2 + x1 -> out (fp32)
    tc_gemm_kernel<true, false, true, false, false>
        <<<dim3(DM / 128, TOK / 256), 256, GEMM_SMEM>>>(
        hid16, w216, b2, x1, out, nullptr, TOK, DM, HID);
}

// round 14
// speedup vs baseline: 1.0137x; 1.0137x over previous
#include <cuda_runtime.h>
#include <cuda_fp16.h>
#include <math.h>
#include <stdint.h>

#define TOK   4096   // B*S tokens
#define DM    1024
#define HID   4096
#define SEQL  2048
#define NB    2
#define NH    16
#define DH    64

// ---------------- scratch (allocation-free: __device__ globals) ----------------
__device__ float g_x1[TOK * DM];                         // residual after attention
__device__ __align__(256) __half g_xnh[TOK * DM];        // LN output, fp16
__device__ __align__(256) __half g_qkv16[3 * TOK * DM];  // fused q|k|v (q pre-scaled)
__device__ __align__(256) __half g_attn16[TOK * DM];
__device__ __align__(256) __half g_hid16[TOK * HID];
// weights transposed to [N,K] fp16
__device__ __align__(256) __half g_wqkv16[3 * DM * DM];  // fused wq|wk|wv rows
__device__ __align__(256) __half g_wo16[DM * DM];
__device__ __align__(256) __half g_w116[DM * HID];
__device__ __align__(256) __half g_w216[HID * DM];

#define SC_LOG2E 0.1803368801111f   // 0.125 * log2(e), folded into Q

// ---------------- base-target PTX helpers ----------------
__device__ __forceinline__ uint32_t smem_u32(const void* p) {
    uint32_t a;
    asm("{ .reg .u64 t; cvta.to.shared.u64 t, %1; cvt.u32.u64 %0, t; }"
        : "=r"(a) : "l"(p));
    return a;
}
__device__ __forceinline__ void cpa16(uint32_t s, const void* g) {
    asm volatile("cp.async.cg.shared.global [%0], [%1], 16;" :: "r"(s), "l"(g));
}
#define CP_COMMIT() asm volatile("cp.async.commit_group;" ::: "memory")
#define CP_WAIT(n)  asm volatile("cp.async.wait_group %0;" :: "n"(n) : "memory")

__device__ __forceinline__ void ldm_x4(uint32_t* r, uint32_t addr) {
    asm volatile("ldmatrix.sync.aligned.m8n8.x4.shared.b16 {%0,%1,%2,%3}, [%4];"
                 : "=r"(r[0]), "=r"(r[1]), "=r"(r[2]), "=r"(r[3]) : "r"(addr));
}
__device__ __forceinline__ void ldm_x4_t(uint32_t* r, uint32_t addr) {
    asm volatile("ldmatrix.sync.aligned.m8n8.x4.trans.shared.b16 {%0,%1,%2,%3}, [%4];"
                 : "=r"(r[0]), "=r"(r[1]), "=r"(r[2]), "=r"(r[3]) : "r"(addr));
}
__device__ __forceinline__ void mma_f16(float* d, const uint32_t* a, const uint32_t* b) {
    asm volatile(
        "mma.sync.aligned.m16n8k16.row.col.f32.f16.f16.f32 "
        "{%0,%1,%2,%3}, {%4,%5,%6,%7}, {%8,%9}, {%0,%1,%2,%3};"
        : "+f"(d[0]), "+f"(d[1]), "+f"(d[2]), "+f"(d[3])
        : "r"(a[0]), "r"(a[1]), "r"(a[2]), "r"(a[3]), "r"(b[0]), "r"(b[1]));
}
__device__ __forceinline__ uint32_t packh2(float lo, float hi) {
    __half2 t = __floats2half2_rn(lo, hi);
    return *(uint32_t*)&t;
}

// ---------------- LayerNorm helper (128 threads per token) ----------------
__device__ __forceinline__ void ln_token(const float* __restrict__ xrow,
                                         const float* __restrict__ gamma,
                                         const float* __restrict__ beta,
                                         __half* __restrict__ orow,
                                         int sub, float* smred)
{
    const float4* xr = (const float4*)xrow;
    float4 v0 = xr[sub];
    float4 v1 = xr[sub + 128];
    float s  = v0.x + v0.y + v0.z + v0.w + v1.x + v1.y + v1.z + v1.w;
    float ss = v0.x*v0.x + v0.y*v0.y + v0.z*v0.z + v0.w*v0.w
             + v1.x*v1.x + v1.y*v1.y + v1.z*v1.z + v1.w*v1.w;
    #pragma unroll
    for (int o = 16; o; o >>= 1) {
        s  += __shfl_xor_sync(0xffffffffu, s,  o);
        ss += __shfl_xor_sync(0xffffffffu, ss, o);
    }
    int w = sub >> 5, ln = sub & 31;
    if (ln == 0) { smred[w] = s; smred[4 + w] = ss; }
    __syncthreads();
    s  = smred[0] + smred[1] + smred[2] + smred[3];
    ss = smred[4] + smred[5] + smred[6] + smred[7];
    float mu   = s * (1.0f / DM);
    float var  = ss * (1.0f / DM) - mu * mu;
    float rstd = rsqrtf(var + 1e-5f);

    const float4* gr = (const float4*)gamma;
    const float4* br = (const float4*)beta;
    #pragma unroll
    for (int u = 0; u < 2; u++) {
        int i = sub + u * 128;
        float4 xv = xr[i], gv = gr[i], bv = br[i];
        float rx = (xv.x - mu) * rstd * gv.x + bv.x;
        float ry = (xv.y - mu) * rstd * gv.y + bv.y;
        float rz = (xv.z - mu) * rstd * gv.z + bv.z;
        float rw = (xv.w - mu) * rstd * gv.w + bv.w;
        uint2 pk;
        pk.x = packh2(rx, ry);
        pk.y = packh2(rz, rw);
        *(uint2*)(orow + i * 4) = pk;
    }
}

// ---------------- standalone LN (for LN2) ----------------
__global__ void ln_kernel(const float* __restrict__ x,
                          const float* __restrict__ gamma,
                          const float* __restrict__ beta,
                          __half* __restrict__ out)
{
    __shared__ float smred[8];
    int t = blockIdx.x;
    ln_token(x + (size_t)t * DM, gamma, beta, out + (size_t)t * DM,
             threadIdx.x, smred);
}

// ------- fused prep: six weight transposes + LN1, one launch ------------------
__global__ void wprep_kernel(const float* __restrict__ wq, const float* __restrict__ wk,
                             const float* __restrict__ wv, const float* __restrict__ wo,
                             const float* __restrict__ w1, const float* __restrict__ w2,
                             __half* __restrict__ owqkv, __half* __restrict__ owo,
                             __half* __restrict__ ow1,   __half* __restrict__ ow2,
                             const float* __restrict__ x,
                             const float* __restrict__ g1, const float* __restrict__ be1,
                             __half* __restrict__ oln)
{
    __shared__ float t[32][33];
    __shared__ float smred[2][8];
    int bid = blockIdx.x;
    int tx = threadIdx.x, ty = threadIdx.y;
    int tid = ty * 32 + tx;

    if (bid >= 12288) {
        int tok = (bid - 12288) * 2 + (tid >> 7);
        ln_token(x + (size_t)tok * DM, g1, be1, oln + (size_t)tok * DM,
                 tid & 127, smred[tid >> 7]);
        return;
    }

    const float* src; __half* dst; int K, N, tile;
    if (bid < 1024)      { src = wq; dst = owqkv;                 K = DM;  N = DM;  tile = bid; }
    else if (bid < 2048) { src = wk; dst = owqkv + DM * DM;       K = DM;  N = DM;  tile = bid - 1024; }
    else if (bid < 3072) { src = wv; dst = owqkv + 2 * DM * DM;   K = DM;  N = DM;  tile = bid - 2048; }
    else if (bid < 4096) { src = wo; dst = owo;                   K = DM;  N = DM;  tile = bid - 3072; }
    else if (bid < 8192) { src = w1; dst = ow1;                   K = DM;  N = HID; tile = bid - 4096; }
    else                 { src = w2; dst = ow2;                   K = HID; N = DM;  tile = bid - 8192; }
    int tpr = N >> 5;
    int n0 = (tile % tpr) * 32, k0 = (tile / tpr) * 32;

    #pragma unroll
    for (int i = 0; i < 4; i++)
        t[ty + i * 8][tx] = src[(size_t)(k0 + ty + i * 8) * N + n0 + tx];
    __syncthreads();
    #pragma unroll
    for (int i = 0; i < 4; i++)
        dst[(size_t)(n0 + ty + i * 8) * K + k0 + tx] = __float2half_rn(t[tx][ty + i * 8]);
}

// ---------------- mma.sync fp16 GEMM, 256x128 CTA tile, 4-stage ring ----------
// (for large-grid GEMMs: QKV, FFN1)
#define GLDA      144
#define GA_BYTES  (256 * GLDA)             // 36864
#define GB_BYTES  (128 * GLDA)             // 18432
#define GSTAGE    (GA_BYTES + GB_BYTES)    // 55296
#define GEMM_SMEM (4 * GSTAGE)             // 221184

template<bool BIAS, bool RELU, bool RES, bool OUTH, bool QKVOUT>
__global__ void __launch_bounds__(256) tc_gemm_kernel(
    const __half* __restrict__ A, const __half* __restrict__ B,
    const float* __restrict__ bias, const float* __restrict__ Res,
    float* __restrict__ Cf, __half* __restrict__ Ch, int M, int N, int K)
{
    extern __shared__ char smem[];
    const uint32_t sb = smem_u32(smem);
    int tid = threadIdx.x;
    int wid = tid >> 5, lane = tid & 31;
    int wm = wid & 3, wn = wid >> 2;
    int m0 = blockIdx.y * 256, n0 = blockIdx.x * 128;

    float acc[4][8][4];
    #pragma unroll
    for (int i = 0; i < 4; i++)
        #pragma unroll
        for (int j = 0; j < 8; j++)
            #pragma unroll
            for (int r = 0; r < 4; r++) acc[i][j][r] = 0.f;

    int nc = K >> 6;

    auto load_chunk = [&](int c, int st) {
        int kc = c << 6;
        uint32_t base = sb + st * GSTAGE;
        #pragma unroll
        for (int i = 0; i < 12; i++) {
            int slot = tid + (i << 8);
            if (slot < 2048) {
                int r = slot >> 3, ch = slot & 7;
                cpa16(base + r * GLDA + ch * 16,
                      A + (size_t)(m0 + r) * K + kc + ch * 8);
            } else {
                int s2 = slot - 2048;
                int r = s2 >> 3, ch = s2 & 7;
                cpa16(base + GA_BYTES + r * GLDA + ch * 16,
                      B + (size_t)(n0 + r) * K + kc + ch * 8);
            }
        }
        CP_COMMIT();
    };

    load_chunk(0, 0);
    load_chunk(1, 1);
    load_chunk(2, 2);

    uint32_t aOff = (uint32_t)((wm * 64 + (lane & 15)) * GLDA + (lane >> 4) * 16);
    int bm = lane >> 3, brr = lane & 7;
    uint32_t bOff = (uint32_t)((wn * 64 + ((bm & 2) ? 8 : 0) + brr) * GLDA
                               + ((bm & 1) ? 16 : 0));

    for (int c = 0; c < nc; c++) {
        int st = c & 3;
        CP_WAIT(2);
        __syncthreads();
        if (c + 3 < nc) load_chunk(c + 3, (c + 3) & 3);
        else            CP_COMMIT();
        uint32_t base = sb + st * GSTAGE;
        #pragma unroll
        for (int ks = 0; ks < 4; ks++) {
            uint32_t kb = ks * 32;
            uint32_t af[4][4], bf[8][2];
            #pragma unroll
            for (int mt = 0; mt < 4; mt++)
                ldm_x4(af[mt], base + aOff + mt * (16 * GLDA) + kb);
            #pragma unroll
            for (int p = 0; p < 4; p++) {
                uint32_t t4[4];
                ldm_x4(t4, base + GA_BYTES + bOff + p * (16 * GLDA) + kb);
                bf[2*p][0] = t4[0]; bf[2*p][1] = t4[1];
                bf[2*p+1][0] = t4[2]; bf[2*p+1][1] = t4[3];
            }
            #pragma unroll
            for (int mt = 0; mt < 4; mt++)
                #pragma unroll
                for (int nt = 0; nt < 8; nt++)
                    mma_f16(acc[mt][nt], af[mt], bf[nt]);
        }
    }

    int g = lane >> 2, tq = lane & 3;
    #pragma unroll
    for (int mt = 0; mt < 4; mt++) {
        int mbase = m0 + wm * 64 + mt * 16 + g;
        #pragma unroll
        for (int nt = 0; nt < 8; nt++) {
            int n = n0 + wn * 64 + nt * 8 + tq * 2;
            float2 v0 = make_float2(acc[mt][nt][0], acc[mt][nt][1]);
            float2 v1 = make_float2(acc[mt][nt][2], acc[mt][nt][3]);
            if (BIAS) {
                float2 bb = *(const float2*)(bias + n);
                v0.x += bb.x; v0.y += bb.y; v1.x += bb.x; v1.y += bb.y;
            }
            if (RELU) {
                v0.x = fmaxf(v0.x, 0.f); v0.y = fmaxf(v0.y, 0.f);
                v1.x = fmaxf(v1.x, 0.f); v1.y = fmaxf(v1.y, 0.f);
            }
            if (RES) {
                float2 q0 = *(const float2*)(Res + (size_t)mbase * N + n);
                float2 q1 = *(const float2*)(Res + (size_t)(mbase + 8) * N + n);
                v0.x += q0.x; v0.y += q0.y; v1.x += q1.x; v1.y += q1.y;
            }
            if (QKVOUT) {
                int which = n >> 10, nn = n & 1023;
                if (which == 0) {
                    v0.x *= SC_LOG2E; v0.y *= SC_LOG2E;
                    v1.x *= SC_LOG2E; v1.y *= SC_LOG2E;
                }
                __half* dst = Ch + (size_t)which * (TOK * DM) + (size_t)mbase * DM + nn;
                *(uint32_t*)dst                    = packh2(v0.x, v0.y);
                *(uint32_t*)(dst + (size_t)8 * DM) = packh2(v1.x, v1.y);
            } else if (OUTH) {
                *(uint32_t*)(Ch + (size_t)mbase * N + n)       = packh2(v0.x, v0.y);
                *(uint32_t*)(Ch + (size_t)(mbase + 8) * N + n) = packh2(v1.x, v1.y);
            } else {
                *(float2*)(Cf + (size_t)mbase * N + n) = v0;
                *(float2*)(Cf + (size_t)(mbase + 8) * N + n) = v1;
            }
        }
    }
}

// ---------------- 128x128-tile GEMM for N=1024 GEMMs (O-proj, FFN2) -----------
// 8 warps (2m x 4n), warp tile 64x32, BK=64, 3-stage ring, 2 CTAs/SM.
#define H_A_BYTES (128 * GLDA)             // 18432
#define H_STAGE   (2 * H_A_BYTES)          // 36864 (A + B)
#define GEMM128_SMEM (3 * H_STAGE)         // 110592

template<bool BIAS, bool RES>
__global__ void __launch_bounds__(256) tc_gemm128_kernel(
    const __half* __restrict__ A, const __half* __restrict__ B,
    const float* __restrict__ bias, const float* __restrict__ Res,
    float* __restrict__ Cf, int M, int N, int K)
{
    extern __shared__ char smem[];
    const uint32_t sb = smem_u32(smem);
    int tid = threadIdx.x;
    int wid = tid >> 5, lane = tid & 31;
    int wm = wid & 1, wn = wid >> 1;                 // warp: rows wm*64, cols wn*32
    int m0 = blockIdx.y * 128, n0 = blockIdx.x * 128;

    float acc[4][4][4];
    #pragma unroll
    for (int i = 0; i < 4; i++)
        #pragma unroll
        for (int j = 0; j < 4; j++)
            #pragma unroll
            for (int r = 0; r < 4; r++) acc[i][j][r] = 0.f;

    int nc = K >> 6;

    auto load_chunk = [&](int c, int st) {
        int kc = c << 6;
        uint32_t base = sb + st * H_STAGE;
        #pragma unroll
        for (int i = 0; i < 8; i++) {
            int slot = tid + (i << 8);
            if (slot < 1024) {                 // A: 128 rows x 8 chunks
                int r = slot >> 3, ch = slot & 7;
                cpa16(base + r * GLDA + ch * 16,
                      A + (size_t)(m0 + r) * K + kc + ch * 8);
            } else {                           // B: 128 rows x 8 chunks
                int s2 = slot - 1024;
                int r = s2 >> 3, ch = s2 & 7;
                cpa16(base + H_A_BYTES + r * GLDA + ch * 16,
                      B + (size_t)(n0 + r) * K + kc + ch * 8);
            }
        }
        CP_COMMIT();
    };

    load_chunk(0, 0);
    load_chunk(1, 1);

    uint32_t aOff = (uint32_t)((wm * 64 + (lane & 15)) * GLDA + (lane >> 4) * 16);
    int bm = lane >> 3, brr = lane & 7;
    uint32_t bOff = (uint32_t)((wn * 32 + ((bm & 2) ? 8 : 0) + brr) * GLDA
                               + ((bm & 1) ? 16 : 0));

    for (int c = 0; c < nc; c++) {
        int st = c % 3;
        CP_WAIT(1);
        __syncthreads();
        // prefetch AFTER barrier: stage (c+2)%3 == (c-1)%3 already consumed.
        if (c + 2 < nc) load_chunk(c + 2, (c + 2) % 3);
        else            CP_COMMIT();
        uint32_t base = sb + st * H_STAGE;
        #pragma unroll
        for (int ks = 0; ks < 4; ks++) {
            uint32_t kb = ks * 32;
            uint32_t af[4][4], bf[4][2];
            #pragma unroll
            for (int mt = 0; mt < 4; mt++)
                ldm_x4(af[mt], base + aOff + mt * (16 * GLDA) + kb);
            #pragma unroll
            for (int p = 0; p < 2; p++) {
                uint32_t t4[4];
                ldm_x4(t4, base + H_A_BYTES + bOff + p * (16 * GLDA) + kb);
                bf[2*p][0] = t4[0]; bf[2*p][1] = t4[1];
                bf[2*p+1][0] = t4[2]; bf[2*p+1][1] = t4[3];
            }
            #pragma unroll
            for (int mt = 0; mt < 4; mt++)
                #pragma unroll
                for (int nt = 0; nt < 4; nt++)
                    mma_f16(acc[mt][nt], af[mt], bf[nt]);
        }
    }

    int g = lane >> 2, tq = lane & 3;
    #pragma unroll
    for (int mt = 0; mt < 4; mt++) {
        int mbase = m0 + wm * 64 + mt * 16 + g;
        #pragma unroll
        for (int nt = 0; nt < 4; nt++) {
            int n = n0 + wn * 32 + nt * 8 + tq * 2;
            float2 v0 = make_float2(acc[mt][nt][0], acc[mt][nt][1]);
            float2 v1 = make_float2(acc[mt][nt][2], acc[mt][nt][3]);
            if (BIAS) {
                float2 bb = *(const float2*)(bias + n);
                v0.x += bb.x; v0.y += bb.y; v1.x += bb.x; v1.y += bb.y;
            }
            if (RES) {
                float2 q0 = *(const float2*)(Res + (size_t)mbase * N + n);
                float2 q1 = *(const float2*)(Res + (size_t)(mbase + 8) * N + n);
                v0.x += q0.x; v0.y += q0.y; v1.x += q1.x; v1.y += q1.y;
            }
            *(float2*)(Cf + (size_t)mbase * N + n) = v0;
            *(float2*)(Cf + (size_t)(mbase + 8) * N + n) = v1;
        }
    }
}

// ---------------- tensor-core flash attention (fp16, base-2 softmax) ----------
// R11 config: 128 queries, 256 threads, 3 KV stages, one sync per tile.
#define ALD  144
#define ATB  (64 * ALD)
#define QTB  (128 * ALD)
#define ASTG (2 * ATB)              // K, V per stage
#define ATT_SMEM (QTB + 3 * ASTG)   // 73728

__global__ void __launch_bounds__(256) attn_tc_kernel(
    const __half* __restrict__ Q, const __half* __restrict__ K,
    const __half* __restrict__ V, __half* __restrict__ O)
{
    extern __shared__ char smc[];
    const uint32_t sb = smem_u32(smc);
    int qt = (int)gridDim.x - 1 - (int)blockIdx.x;
    int h = blockIdx.y, b = blockIdx.z;
    int tid = threadIdx.x;
    int wm = tid >> 5, lane = tid & 31;

    auto load_kv = [&](int t, int st) {
        uint32_t base = sb + QTB + st * ASTG;
        #pragma unroll
        for (int i = 0; i < 2; i++) {
            int slot = tid * 2 + i;
            int r = slot >> 3, c = slot & 7;
            size_t gk = (size_t)(b * SEQL + t * 64 + r) * DM + h * DH + c * 8;
            uint32_t so = (uint32_t)(r * ALD + c * 16);
            cpa16(base + so,       K + gk);
            cpa16(base + ATB + so, V + gk);
        }
    };

    #pragma unroll
    for (int i = 0; i < 4; i++) {
        int slot = tid * 4 + i;
        int r = slot >> 3, c = slot & 7;
        size_t gq = (size_t)(b * SEQL + qt * 128 + r) * DM + h * DH + c * 8;
        cpa16(sb + (uint32_t)(r * ALD + c * 16), Q + gq);
    }
    load_kv(0, 0);
    CP_COMMIT();
    load_kv(1, 1);
    CP_COMMIT();

    float oacc[8][4];
    #pragma unroll
    for (int nt = 0; nt < 8; nt++)
        #pragma unroll
        for (int j = 0; j < 4; j++) oacc[nt][j] = 0.f;
    float mrow[2] = {-INFINITY, -INFINITY};
    float lrow[2] = {0.f, 0.f};

    uint32_t aOff = (uint32_t)((wm * 16 + (lane & 15)) * ALD + (lane >> 4) * 16);
    int bm = lane >> 3, brr = lane & 7;
    uint32_t bOff = (uint32_t)((((bm & 2) ? 8 : 0) + brr) * ALD + ((bm & 1) ? 16 : 0));
    uint32_t vtOff = (uint32_t)((lane & 15) * ALD + (lane >> 4) * 16);

    int ntile = 2 * qt + 2;
    for (int t = 0; t < ntile; t++) {
        int st = t % 3;
        CP_WAIT(1);
        __syncthreads();
        if (t + 2 < ntile) { load_kv(t + 2, (t + 2) % 3); CP_COMMIT(); }
        else               { CP_COMMIT(); }

        uint32_t kbase = sb + QTB + st * ASTG;
        uint32_t vbase = kbase + ATB;

        float sacc[8][4];
        #pragma unroll
        for (int nt = 0; nt < 8; nt++)
            #pragma unroll
            for (int j = 0; j < 4; j++) sacc[nt][j] = 0.f;

        #pragma unroll
        for (int kt = 0; kt < 4; kt++) {
            uint32_t kb = kt * 32;
            uint32_t a4[4];
            ldm_x4(a4, sb + aOff + kb);
            #pragma unroll
            for (int p = 0; p < 4; p++) {
                uint32_t t4[4];
                ldm_x4(t4, kbase + bOff + p * (16 * ALD) + kb);
                uint32_t b0[2] = {t4[0], t4[1]}, b1[2] = {t4[2], t4[3]};
                mma_f16(sacc[2*p],   a4, b0);
                mma_f16(sacc[2*p+1], a4, b1);
            }
        }

        int g = lane >> 2, colb = (lane & 3) * 2;
        if (t >= 2 * qt) {
            #pragma unroll
            for (int nt = 0; nt < 8; nt++)
                #pragma unroll
                for (int j = 0; j < 4; j++) {
                    int col = t * 64 + nt * 8 + colb + (j & 1);
                    int qr  = qt * 128 + wm * 16 + g + ((j >= 2) ? 8 : 0);
                    if (col > qr) sacc[nt][j] = -1e30f;
                }
        }

        float mt0 = -INFINITY, mt1 = -INFINITY;
        #pragma unroll
        for (int nt = 0; nt < 8; nt++) {
            mt0 = fmaxf(mt0, fmaxf(sacc[nt][0], sacc[nt][1]));
            mt1 = fmaxf(mt1, fmaxf(sacc[nt][2], sacc[nt][3]));
        }
        mt0 = fmaxf(mt0, __shfl_xor_sync(0xffffffffu, mt0, 1));
        mt0 = fmaxf(mt0, __shfl_xor_sync(0xffffffffu, mt0, 2));
        mt1 = fmaxf(mt1, __shfl_xor_sync(0xffffffffu, mt1, 1));
        mt1 = fmaxf(mt1, __shfl_xor_sync(0xffffffffu, mt1, 2));
        float mn0 = fmaxf(mrow[0], mt0), mn1 = fmaxf(mrow[1], mt1);
        float sc0 = exp2f(mrow[0] - mn0), sc1 = exp2f(mrow[1] - mn1);
        mrow[0] = mn0; mrow[1] = mn1;
        #pragma unroll
        for (int nt = 0; nt < 8; nt++) {
            oacc[nt][0] *= sc0; oacc[nt][1] *= sc0;
            oacc[nt][2] *= sc1; oacc[nt][3] *= sc1;
        }

        float lt0 = 0.f, lt1 = 0.f;
        #pragma unroll
        for (int kk = 0; kk < 4; kk++) {
            float p00 = exp2f(sacc[2*kk][0]   - mn0);
            float p01 = exp2f(sacc[2*kk][1]   - mn0);
            float p02 = exp2f(sacc[2*kk][2]   - mn1);
            float p03 = exp2f(sacc[2*kk][3]   - mn1);
            float p10 = exp2f(sacc[2*kk+1][0] - mn0);
            float p11 = exp2f(sacc[2*kk+1][1] - mn0);
            float p12 = exp2f(sacc[2*kk+1][2] - mn1);
            float p13 = exp2f(sacc[2*kk+1][3] - mn1);
            lt0 += (p00 + p01) + (p10 + p11);
            lt1 += (p02 + p03) + (p12 + p13);
            uint32_t pa[4];
            pa[0] = packh2(p00, p01);
            pa[1] = packh2(p02, p03);
            pa[2] = packh2(p10, p11);
            pa[3] = packh2(p12, p13);
            uint32_t rowb = vbase + vtOff + kk * (16 * ALD);
            #pragma unroll
            for (int p = 0; p < 4; p++) {
                uint32_t t4[4];
                ldm_x4_t(t4, rowb + p * 32);
                uint32_t b0[2] = {t4[0], t4[1]}, b1[2] = {t4[2], t4[3]};
                mma_f16(oacc[2*p],   pa, b0);
                mma_f16(oacc[2*p+1], pa, b1);
            }
        }
        lt0 += __shfl_xor_sync(0xffffffffu, lt0, 1);
        lt0 += __shfl_xor_sync(0xffffffffu, lt0, 2);
        lt1 += __shfl_xor_sync(0xffffffffu, lt1, 1);
        lt1 += __shfl_xor_sync(0xffffffffu, lt1, 2);
        lrow[0] = lrow[0] * sc0 + lt0;
        lrow[1] = lrow[1] * sc1 + lt1;
    }

    float inv0 = 1.0f / lrow[0], inv1 = 1.0f / lrow[1];
    int g = lane >> 2, tq = lane & 3;
    int row0 = qt * 128 + wm * 16 + g;
    #pragma unroll
    for (int nt = 0; nt < 8; nt++) {
        int d = h * DH + nt * 8 + tq * 2;
        *(uint32_t*)(O + (size_t)(b * SEQL + row0) * DM + d) =
            packh2(oacc[nt][0] * inv0, oacc[nt][1] * inv0);
        *(uint32_t*)(O + (size_t)(b * SEQL + row0 + 8) * DM + d) =
            packh2(oacc[nt][2] * inv1, oacc[nt][3] * inv1);
    }
}

// ---------------- launch ----------------
extern "C" void kernel_launch(void* const* d_in, const int* in_sizes, int n_in,
                              void* d_out, int out_size)
{
    const float* x   = (const float*)d_in[0];
    const float* wq  = (const float*)d_in[1];
    const float* wk  = (const float*)d_in[2];
    const float* wv  = (const float*)d_in[3];
    const float* wo  = (const float*)d_in[4];
    const float* w1  = (const float*)d_in[5];
    const float* b1  = (const float*)d_in[6];
    const float* w2  = (const float*)d_in[7];
    const float* b2  = (const float*)d_in[8];
    const float* g1  = (const float*)d_in[9];
    const float* be1 = (const float*)d_in[10];
    const float* g2  = (const float*)d_in[11];
    const float* be2 = (const float*)d_in[12];
    float* out = (float*)d_out;

    float* x1;
    cudaGetSymbolAddress((void**)&x1, g_x1);
    __half *xnh, *qkv16, *attn16, *hid16;
    __half *wqkv16, *wo16, *w116, *w216;
    cudaGetSymbolAddress((void**)&xnh,    g_xnh);
    cudaGetSymbolAddress((void**)&qkv16,  g_qkv16);
    cudaGetSymbolAddress((void**)&attn16, g_attn16);
    cudaGetSymbolAddress((void**)&hid16,  g_hid16);
    cudaGetSymbolAddress((void**)&wqkv16, g_wqkv16);
    cudaGetSymbolAddress((void**)&wo16,   g_wo16);
    cudaGetSymbolAddress((void**)&w116,   g_w116);
    cudaGetSymbolAddress((void**)&w216,   g_w216);
    __half* q16 = qkv16;
    __half* k16 = qkv16 + (size_t)TOK * DM;
    __half* v16 = qkv16 + 2 * (size_t)TOK * DM;

    cudaFuncSetAttribute(attn_tc_kernel, cudaFuncAttributeMaxDynamicSharedMemorySize,
                         ATT_SMEM);
    cudaFuncSetAttribute(tc_gemm_kernel<false, false, false, true, true>,
                         cudaFuncAttributeMaxDynamicSharedMemorySize, GEMM_SMEM);
    cudaFuncSetAttribute(tc_gemm_kernel<true, true, false, true, false>,
                         cudaFuncAttributeMaxDynamicSharedMemorySize, GEMM_SMEM);
    cudaFuncSetAttribute(tc_gemm128_kernel<false, true>,
                         cudaFuncAttributeMaxDynamicSharedMemorySize, GEMM128_SMEM);
    cudaFuncSetAttribute(tc_gemm128_kernel<true, true>,
                         cudaFuncAttributeMaxDynamicSharedMemorySize, GEMM128_SMEM);

    // fused weight prep + LN1 (single launch)
    wprep_kernel<<<14336, dim3(32, 8)>>>(wq, wk, wv, wo, w1, w2,
                                         wqkv16, wo16, w116, w216,
                                         x, g1, be1, xnh);

    // fused QKV projection (N=3072) -> q|k|v fp16 (q pre-scaled)
    tc_gemm_kernel<false, false, false, true, true>
        <<<dim3(3 * DM / 128, TOK / 256), 256, GEMM_SMEM>>>(
        xnh, wqkv16, nullptr, nullptr, nullptr, qkv16, TOK, 3 * DM, DM);

    // tensor-core attention -> fp16
    attn_tc_kernel<<<dim3(SEQL / 128, NH, NB), 256, ATT_SMEM>>>(q16, k16, v16, attn16);

    // O projection + residual(x) -> x1 (fp32) — 128x128 tiles, grid 8x32=256
    tc_gemm128_kernel<false, true>
        <<<dim3(DM / 128, TOK / 128), 256, GEMM128_SMEM>>>(
        attn16, wo16, nullptr, x, x1, TOK, DM, DM);

    // LN2 -> fp16
    ln_kernel<<<TOK, 128>>>(x1, g2, be2, xnh);

    // FFN1: relu(xn @ w1 + b1) -> fp16 hid
    tc_gemm_kernel<true, true, false, true, false>
        <<<dim3(HID / 128, TOK / 256), 256, GEMM_SMEM>>>(
        xnh, w116, b1, nullptr, nullptr, hid16, TOK, HID, DM);

    // FFN2: hid @ w2 + b2 + x1 -> out (fp32) — 128x128 tiles, grid 8x32=256
    tc_gemm128_kernel<true, true>
        <<<dim3(DM / 128, TOK / 128), 256, GEMM128_SMEM>>>(
        hid16, w216, b2, x1, out, TOK, DM, HID);
}

// round 15
// speedup vs baseline: 1.0168x; 1.0030x over previous
#include <cuda_runtime.h>
#include <cuda_fp16.h>
#include <math.h>
#include <stdint.h>

#define TOK   4096   // B*S tokens
#define DM    1024
#define HID   4096
#define SEQL  2048
#define NB    2
#define NH    16
#define DH    64

// ---------------- scratch (allocation-free: __device__ globals) ----------------
__device__ float g_x1[TOK * DM];                         // residual after attention
__device__ __align__(256) __half g_xnh[TOK * DM];        // LN output, fp16
__device__ __align__(256) __half g_qkv16[3 * TOK * DM];  // fused q|k|v (q pre-scaled)
__device__ __align__(256) __half g_attn16[TOK * DM];
__device__ __align__(256) __half g_hid16[TOK * HID];
// weights transposed to [N,K] fp16
__device__ __align__(256) __half g_wqkv16[3 * DM * DM];  // fused wq|wk|wv rows
__device__ __align__(256) __half g_wo16[DM * DM];
__device__ __align__(256) __half g_w116[DM * HID];
__device__ __align__(256) __half g_w216[HID * DM];

#define SC_LOG2E 0.1803368801111f   // 0.125 * log2(e), folded into Q

// ---------------- base-target PTX helpers ----------------
__device__ __forceinline__ uint32_t smem_u32(const void* p) {
    uint32_t a;
    asm("{ .reg .u64 t; cvta.to.shared.u64 t, %1; cvt.u32.u64 %0, t; }"
        : "=r"(a) : "l"(p));
    return a;
}
__device__ __forceinline__ void cpa16(uint32_t s, const void* g) {
    asm volatile("cp.async.cg.shared.global [%0], [%1], 16;" :: "r"(s), "l"(g));
}
#define CP_COMMIT() asm volatile("cp.async.commit_group;" ::: "memory")
#define CP_WAIT(n)  asm volatile("cp.async.wait_group %0;" :: "n"(n) : "memory")

__device__ __forceinline__ void ldm_x4(uint32_t* r, uint32_t addr) {
    asm volatile("ldmatrix.sync.aligned.m8n8.x4.shared.b16 {%0,%1,%2,%3}, [%4];"
                 : "=r"(r[0]), "=r"(r[1]), "=r"(r[2]), "=r"(r[3]) : "r"(addr));
}
__device__ __forceinline__ void ldm_x4_t(uint32_t* r, uint32_t addr) {
    asm volatile("ldmatrix.sync.aligned.m8n8.x4.trans.shared.b16 {%0,%1,%2,%3}, [%4];"
                 : "=r"(r[0]), "=r"(r[1]), "=r"(r[2]), "=r"(r[3]) : "r"(addr));
}
__device__ __forceinline__ void mma_f16(float* d, const uint32_t* a, const uint32_t* b) {
    asm volatile(
        "mma.sync.aligned.m16n8k16.row.col.f32.f16.f16.f32 "
        "{%0,%1,%2,%3}, {%4,%5,%6,%7}, {%8,%9}, {%0,%1,%2,%3};"
        : "+f"(d[0]), "+f"(d[1]), "+f"(d[2]), "+f"(d[3])
        : "r"(a[0]), "r"(a[1]), "r"(a[2]), "r"(a[3]), "r"(b[0]), "r"(b[1]));
}
__device__ __forceinline__ uint32_t packh2(float lo, float hi) {
    __half2 t = __floats2half2_rn(lo, hi);
    return *(uint32_t*)&t;
}

// ---------------- LayerNorm helper (128 threads per token) ----------------
__device__ __forceinline__ void ln_token(const float* __restrict__ xrow,
                                         const float* __restrict__ gamma,
                                         const float* __restrict__ beta,
                                         __half* __restrict__ orow,
                                         int sub, float* smred)
{
    const float4* xr = (const float4*)xrow;
    float4 v0 = xr[sub];
    float4 v1 = xr[sub + 128];
    float s  = v0.x + v0.y + v0.z + v0.w + v1.x + v1.y + v1.z + v1.w;
    float ss = v0.x*v0.x + v0.y*v0.y + v0.z*v0.z + v0.w*v0.w
             + v1.x*v1.x + v1.y*v1.y + v1.z*v1.z + v1.w*v1.w;
    #pragma unroll
    for (int o = 16; o; o >>= 1) {
        s  += __shfl_xor_sync(0xffffffffu, s,  o);
        ss += __shfl_xor_sync(0xffffffffu, ss, o);
    }
    int w = sub >> 5, ln = sub & 31;
    if (ln == 0) { smred[w] = s; smred[4 + w] = ss; }
    __syncthreads();
    s  = smred[0] + smred[1] + smred[2] + smred[3];
    ss = smred[4] + smred[5] + smred[6] + smred[7];
    float mu   = s * (1.0f / DM);
    float var  = ss * (1.0f / DM) - mu * mu;
    float rstd = rsqrtf(var + 1e-5f);

    const float4* gr = (const float4*)gamma;
    const float4* br = (const float4*)beta;
    #pragma unroll
    for (int u = 0; u < 2; u++) {
        int i = sub + u * 128;
        float4 xv = xr[i], gv = gr[i], bv = br[i];
        float rx = (xv.x - mu) * rstd * gv.x + bv.x;
        float ry = (xv.y - mu) * rstd * gv.y + bv.y;
        float rz = (xv.z - mu) * rstd * gv.z + bv.z;
        float rw = (xv.w - mu) * rstd * gv.w + bv.w;
        uint2 pk;
        pk.x = packh2(rx, ry);
        pk.y = packh2(rz, rw);
        *(uint2*)(orow + i * 4) = pk;
    }
}

// ---------------- standalone LN (for LN2) ----------------
__global__ void ln_kernel(const float* __restrict__ x,
                          const float* __restrict__ gamma,
                          const float* __restrict__ beta,
                          __half* __restrict__ out)
{
    __shared__ float smred[8];
    int t = blockIdx.x;
    ln_token(x + (size_t)t * DM, gamma, beta, out + (size_t)t * DM,
             threadIdx.x, smred);
}

// ------- fused prep: six weight transposes + LN1, one launch ------------------
__global__ void wprep_kernel(const float* __restrict__ wq, const float* __restrict__ wk,
                             const float* __restrict__ wv, const float* __restrict__ wo,
                             const float* __restrict__ w1, const float* __restrict__ w2,
                             __half* __restrict__ owqkv, __half* __restrict__ owo,
                             __half* __restrict__ ow1,   __half* __restrict__ ow2,
                             const float* __restrict__ x,
                             const float* __restrict__ g1, const float* __restrict__ be1,
                             __half* __restrict__ oln)
{
    __shared__ float t[32][33];
    __shared__ float smred[2][8];
    int bid = blockIdx.x;
    int tx = threadIdx.x, ty = threadIdx.y;
    int tid = ty * 32 + tx;

    if (bid >= 12288) {
        int tok = (bid - 12288) * 2 + (tid >> 7);
        ln_token(x + (size_t)tok * DM, g1, be1, oln + (size_t)tok * DM,
                 tid & 127, smred[tid >> 7]);
        return;
    }

    const float* src; __half* dst; int K, N, tile;
    if (bid < 1024)      { src = wq; dst = owqkv;                 K = DM;  N = DM;  tile = bid; }
    else if (bid < 2048) { src = wk; dst = owqkv + DM * DM;       K = DM;  N = DM;  tile = bid - 1024; }
    else if (bid < 3072) { src = wv; dst = owqkv + 2 * DM * DM;   K = DM;  N = DM;  tile = bid - 2048; }
    else if (bid < 4096) { src = wo; dst = owo;                   K = DM;  N = DM;  tile = bid - 3072; }
    else if (bid < 8192) { src = w1; dst = ow1;                   K = DM;  N = HID; tile = bid - 4096; }
    else                 { src = w2; dst = ow2;                   K = HID; N = DM;  tile = bid - 8192; }
    int tpr = N >> 5;
    int n0 = (tile % tpr) * 32, k0 = (tile / tpr) * 32;

    #pragma unroll
    for (int i = 0; i < 4; i++)
        t[ty + i * 8][tx] = src[(size_t)(k0 + ty + i * 8) * N + n0 + tx];
    __syncthreads();
    #pragma unroll
    for (int i = 0; i < 4; i++)
        dst[(size_t)(n0 + ty + i * 8) * K + k0 + tx] = __float2half_rn(t[tx][ty + i * 8]);
}

// ---------------- mma.sync fp16 GEMM, 256x128 CTA tile, 4-stage ring ----------
// (for large-grid GEMMs: QKV, FFN1)
#define GLDA      144
#define GA_BYTES  (256 * GLDA)             // 36864
#define GB_BYTES  (128 * GLDA)             // 18432
#define GSTAGE    (GA_BYTES + GB_BYTES)    // 55296
#define GEMM_SMEM (4 * GSTAGE)             // 221184

template<bool BIAS, bool RELU, bool RES, bool OUTH, bool QKVOUT>
__global__ void __launch_bounds__(256) tc_gemm_kernel(
    const __half* __restrict__ A, const __half* __restrict__ B,
    const float* __restrict__ bias, const float* __restrict__ Res,
    float* __restrict__ Cf, __half* __restrict__ Ch, int M, int N, int K)
{
    extern __shared__ char smem[];
    const uint32_t sb = smem_u32(smem);
    int tid = threadIdx.x;
    int wid = tid >> 5, lane = tid & 31;
    int wm = wid & 3, wn = wid >> 2;
    int m0 = blockIdx.y * 256, n0 = blockIdx.x * 128;

    float acc[4][8][4];
    #pragma unroll
    for (int i = 0; i < 4; i++)
        #pragma unroll
        for (int j = 0; j < 8; j++)
            #pragma unroll
            for (int r = 0; r < 4; r++) acc[i][j][r] = 0.f;

    int nc = K >> 6;

    auto load_chunk = [&](int c, int st) {
        int kc = c << 6;
        uint32_t base = sb + st * GSTAGE;
        #pragma unroll
        for (int i = 0; i < 12; i++) {
            int slot = tid + (i << 8);
            if (slot < 2048) {
                int r = slot >> 3, ch = slot & 7;
                cpa16(base + r * GLDA + ch * 16,
                      A + (size_t)(m0 + r) * K + kc + ch * 8);
            } else {
                int s2 = slot - 2048;
                int r = s2 >> 3, ch = s2 & 7;
                cpa16(base + GA_BYTES + r * GLDA + ch * 16,
                      B + (size_t)(n0 + r) * K + kc + ch * 8);
            }
        }
        CP_COMMIT();
    };

    load_chunk(0, 0);
    load_chunk(1, 1);
    load_chunk(2, 2);

    uint32_t aOff = (uint32_t)((wm * 64 + (lane & 15)) * GLDA + (lane >> 4) * 16);
    int bm = lane >> 3, brr = lane & 7;
    uint32_t bOff = (uint32_t)((wn * 64 + ((bm & 2) ? 8 : 0) + brr) * GLDA
                               + ((bm & 1) ? 16 : 0));

    for (int c = 0; c < nc; c++) {
        int st = c & 3;
        CP_WAIT(2);
        __syncthreads();
        if (c + 3 < nc) load_chunk(c + 3, (c + 3) & 3);
        else            CP_COMMIT();
        uint32_t base = sb + st * GSTAGE;
        #pragma unroll
        for (int ks = 0; ks < 4; ks++) {
            uint32_t kb = ks * 32;
            uint32_t af[4][4], bf[8][2];
            #pragma unroll
            for (int mt = 0; mt < 4; mt++)
                ldm_x4(af[mt], base + aOff + mt * (16 * GLDA) + kb);
            #pragma unroll
            for (int p = 0; p < 4; p++) {
                uint32_t t4[4];
                ldm_x4(t4, base + GA_BYTES + bOff + p * (16 * GLDA) + kb);
                bf[2*p][0] = t4[0]; bf[2*p][1] = t4[1];
                bf[2*p+1][0] = t4[2]; bf[2*p+1][1] = t4[3];
            }
            #pragma unroll
            for (int mt = 0; mt < 4; mt++)
                #pragma unroll
                for (int nt = 0; nt < 8; nt++)
                    mma_f16(acc[mt][nt], af[mt], bf[nt]);
        }
    }

    int g = lane >> 2, tq = lane & 3;
    #pragma unroll
    for (int mt = 0; mt < 4; mt++) {
        int mbase = m0 + wm * 64 + mt * 16 + g;
        #pragma unroll
        for (int nt = 0; nt < 8; nt++) {
            int n = n0 + wn * 64 + nt * 8 + tq * 2;
            float2 v0 = make_float2(acc[mt][nt][0], acc[mt][nt][1]);
            float2 v1 = make_float2(acc[mt][nt][2], acc[mt][nt][3]);
            if (BIAS) {
                float2 bb = *(const float2*)(bias + n);
                v0.x += bb.x; v0.y += bb.y; v1.x += bb.x; v1.y += bb.y;
            }
            if (RELU) {
                v0.x = fmaxf(v0.x, 0.f); v0.y = fmaxf(v0.y, 0.f);
                v1.x = fmaxf(v1.x, 0.f); v1.y = fmaxf(v1.y, 0.f);
            }
            if (RES) {
                float2 q0 = *(const float2*)(Res + (size_t)mbase * N + n);
                float2 q1 = *(const float2*)(Res + (size_t)(mbase + 8) * N + n);
                v0.x += q0.x; v0.y += q0.y; v1.x += q1.x; v1.y += q1.y;
            }
            if (QKVOUT) {
                int which = n >> 10, nn = n & 1023;
                if (which == 0) {
                    v0.x *= SC_LOG2E; v0.y *= SC_LOG2E;
                    v1.x *= SC_LOG2E; v1.y *= SC_LOG2E;
                }
                __half* dst = Ch + (size_t)which * (TOK * DM) + (size_t)mbase * DM + nn;
                *(uint32_t*)dst                    = packh2(v0.x, v0.y);
                *(uint32_t*)(dst + (size_t)8 * DM) = packh2(v1.x, v1.y);
            } else if (OUTH) {
                *(uint32_t*)(Ch + (size_t)mbase * N + n)       = packh2(v0.x, v0.y);
                *(uint32_t*)(Ch + (size_t)(mbase + 8) * N + n) = packh2(v1.x, v1.y);
            } else {
                *(float2*)(Cf + (size_t)mbase * N + n) = v0;
                *(float2*)(Cf + (size_t)(mbase + 8) * N + n) = v1;
            }
        }
    }
}

// ---------------- 128x128-tile GEMM for N=1024 GEMMs (O-proj, FFN2) -----------
#define H_A_BYTES (128 * GLDA)             // 18432
#define H_STAGE   (2 * H_A_BYTES)          // 36864 (A + B)
#define GEMM128_SMEM (3 * H_STAGE)         // 110592

template<bool BIAS, bool RES>
__global__ void __launch_bounds__(256) tc_gemm128_kernel(
    const __half* __restrict__ A, const __half* __restrict__ B,
    const float* __restrict__ bias, const float* __restrict__ Res,
    float* __restrict__ Cf, int M, int N, int K)
{
    extern __shared__ char smem[];
    const uint32_t sb = smem_u32(smem);
    int tid = threadIdx.x;
    int wid = tid >> 5, lane = tid & 31;
    int wm = wid & 1, wn = wid >> 1;
    int m0 = blockIdx.y * 128, n0 = blockIdx.x * 128;

    float acc[4][4][4];
    #pragma unroll
    for (int i = 0; i < 4; i++)
        #pragma unroll
        for (int j = 0; j < 4; j++)
            #pragma unroll
            for (int r = 0; r < 4; r++) acc[i][j][r] = 0.f;

    int nc = K >> 6;

    auto load_chunk = [&](int c, int st) {
        int kc = c << 6;
        uint32_t base = sb + st * H_STAGE;
        #pragma unroll
        for (int i = 0; i < 8; i++) {
            int slot = tid + (i << 8);
            if (slot < 1024) {
                int r = slot >> 3, ch = slot & 7;
                cpa16(base + r * GLDA + ch * 16,
                      A + (size_t)(m0 + r) * K + kc + ch * 8);
            } else {
                int s2 = slot - 1024;
                int r = s2 >> 3, ch = s2 & 7;
                cpa16(base + H_A_BYTES + r * GLDA + ch * 16,
                      B + (size_t)(n0 + r) * K + kc + ch * 8);
            }
        }
        CP_COMMIT();
    };

    load_chunk(0, 0);
    load_chunk(1, 1);

    uint32_t aOff = (uint32_t)((wm * 64 + (lane & 15)) * GLDA + (lane >> 4) * 16);
    int bm = lane >> 3, brr = lane & 7;
    uint32_t bOff = (uint32_t)((wn * 32 + ((bm & 2) ? 8 : 0) + brr) * GLDA
                               + ((bm & 1) ? 16 : 0));

    for (int c = 0; c < nc; c++) {
        int st = c % 3;
        CP_WAIT(1);
        __syncthreads();
        if (c + 2 < nc) load_chunk(c + 2, (c + 2) % 3);
        else            CP_COMMIT();
        uint32_t base = sb + st * H_STAGE;
        #pragma unroll
        for (int ks = 0; ks < 4; ks++) {
            uint32_t kb = ks * 32;
            uint32_t af[4][4], bf[4][2];
            #pragma unroll
            for (int mt = 0; mt < 4; mt++)
                ldm_x4(af[mt], base + aOff + mt * (16 * GLDA) + kb);
            #pragma unroll
            for (int p = 0; p < 2; p++) {
                uint32_t t4[4];
                ldm_x4(t4, base + H_A_BYTES + bOff + p * (16 * GLDA) + kb);
                bf[2*p][0] = t4[0]; bf[2*p][1] = t4[1];
                bf[2*p+1][0] = t4[2]; bf[2*p+1][1] = t4[3];
            }
            #pragma unroll
            for (int mt = 0; mt < 4; mt++)
                #pragma unroll
                for (int nt = 0; nt < 4; nt++)
                    mma_f16(acc[mt][nt], af[mt], bf[nt]);
        }
    }

    int g = lane >> 2, tq = lane & 3;
    #pragma unroll
    for (int mt = 0; mt < 4; mt++) {
        int mbase = m0 + wm * 64 + mt * 16 + g;
        #pragma unroll
        for (int nt = 0; nt < 4; nt++) {
            int n = n0 + wn * 32 + nt * 8 + tq * 2;
            float2 v0 = make_float2(acc[mt][nt][0], acc[mt][nt][1]);
            float2 v1 = make_float2(acc[mt][nt][2], acc[mt][nt][3]);
            if (BIAS) {
                float2 bb = *(const float2*)(bias + n);
                v0.x += bb.x; v0.y += bb.y; v1.x += bb.x; v1.y += bb.y;
            }
            if (RES) {
                float2 q0 = *(const float2*)(Res + (size_t)mbase * N + n);
                float2 q1 = *(const float2*)(Res + (size_t)(mbase + 8) * N + n);
                v0.x += q0.x; v0.y += q0.y; v1.x += q1.x; v1.y += q1.y;
            }
            *(float2*)(Cf + (size_t)mbase * N + n) = v0;
            *(float2*)(Cf + (size_t)(mbase + 8) * N + n) = v1;
        }
    }
}

// ---------------- tensor-core flash attention (fp16, base-2 softmax) ----------
// 128 queries, 256 threads, 4 KV stages, one sync per tile, deferred l-reduce.
#define ALD  144
#define ATB  (64 * ALD)
#define QTB  (128 * ALD)
#define ASTG (2 * ATB)              // K, V per stage
#define ATT_SMEM (QTB + 4 * ASTG)   // 92160

__global__ void __launch_bounds__(256) attn_tc_kernel(
    const __half* __restrict__ Q, const __half* __restrict__ K,
    const __half* __restrict__ V, __half* __restrict__ O)
{
    extern __shared__ char smc[];
    const uint32_t sb = smem_u32(smc);
    int qt = (int)gridDim.x - 1 - (int)blockIdx.x;
    int h = blockIdx.y, b = blockIdx.z;
    int tid = threadIdx.x;
    int wm = tid >> 5, lane = tid & 31;

    auto load_kv = [&](int t, int st) {
        uint32_t base = sb + QTB + st * ASTG;
        #pragma unroll
        for (int i = 0; i < 2; i++) {
            int slot = tid * 2 + i;
            int r = slot >> 3, c = slot & 7;
            size_t gk = (size_t)(b * SEQL + t * 64 + r) * DM + h * DH + c * 8;
            uint32_t so = (uint32_t)(r * ALD + c * 16);
            cpa16(base + so,       K + gk);
            cpa16(base + ATB + so, V + gk);
        }
    };

    int ntile = 2 * qt + 2;

    #pragma unroll
    for (int i = 0; i < 4; i++) {
        int slot = tid * 4 + i;
        int r = slot >> 3, c = slot & 7;
        size_t gq = (size_t)(b * SEQL + qt * 128 + r) * DM + h * DH + c * 8;
        cpa16(sb + (uint32_t)(r * ALD + c * 16), Q + gq);
    }
    load_kv(0, 0);
    CP_COMMIT();
    if (ntile > 1) load_kv(1, 1);
    CP_COMMIT();
    if (ntile > 2) load_kv(2, 2);
    CP_COMMIT();

    float oacc[8][4];
    #pragma unroll
    for (int nt = 0; nt < 8; nt++)
        #pragma unroll
        for (int j = 0; j < 4; j++) oacc[nt][j] = 0.f;
    float mrow[2] = {-INFINITY, -INFINITY};
    float lpart[2] = {0.f, 0.f};          // per-lane partial row sums (deferred)

    uint32_t aOff = (uint32_t)((wm * 16 + (lane & 15)) * ALD + (lane >> 4) * 16);
    int bm = lane >> 3, brr = lane & 7;
    uint32_t bOff = (uint32_t)((((bm & 2) ? 8 : 0) + brr) * ALD + ((bm & 1) ? 16 : 0));
    uint32_t vtOff = (uint32_t)((lane & 15) * ALD + (lane >> 4) * 16);

    for (int t = 0; t < ntile; t++) {
        int st = t & 3;
        CP_WAIT(2);
        __syncthreads();
        // prefetch after barrier: stage (t+3)&3 == (t-1)&3 already consumed.
        if (t + 3 < ntile) { load_kv(t + 3, (t + 3) & 3); CP_COMMIT(); }
        else               { CP_COMMIT(); }

        uint32_t kbase = sb + QTB + st * ASTG;
        uint32_t vbase = kbase + ATB;

        // ---- scores (pre-scaled Q -> already base-2) ----
        float sacc[8][4];
        #pragma unroll
        for (int nt = 0; nt < 8; nt++)
            #pragma unroll
            for (int j = 0; j < 4; j++) sacc[nt][j] = 0.f;

        #pragma unroll
        for (int kt = 0; kt < 4; kt++) {
            uint32_t kb = kt * 32;
            uint32_t a4[4];
            ldm_x4(a4, sb + aOff + kb);
            #pragma unroll
            for (int p = 0; p < 4; p++) {
                uint32_t t4[4];
                ldm_x4(t4, kbase + bOff + p * (16 * ALD) + kb);
                uint32_t b0[2] = {t4[0], t4[1]}, b1[2] = {t4[2], t4[3]};
                mma_f16(sacc[2*p],   a4, b0);
                mma_f16(sacc[2*p+1], a4, b1);
            }
        }

        // ---- causal mask only on diagonal tiles ----
        int g = lane >> 2, colb = (lane & 3) * 2;
        if (t >= 2 * qt) {
            #pragma unroll
            for (int nt = 0; nt < 8; nt++)
                #pragma unroll
                for (int j = 0; j < 4; j++) {
                    int col = t * 64 + nt * 8 + colb + (j & 1);
                    int qr  = qt * 128 + wm * 16 + g + ((j >= 2) ? 8 : 0);
                    if (col > qr) sacc[nt][j] = -1e30f;
                }
        }

        // ---- row max + rescale factors ----
        float mt0 = -INFINITY, mt1 = -INFINITY;
        #pragma unroll
        for (int nt = 0; nt < 8; nt++) {
            mt0 = fmaxf(mt0, fmaxf(sacc[nt][0], sacc[nt][1]));
            mt1 = fmaxf(mt1, fmaxf(sacc[nt][2], sacc[nt][3]));
        }
        mt0 = fmaxf(mt0, __shfl_xor_sync(0xffffffffu, mt0, 1));
        mt0 = fmaxf(mt0, __shfl_xor_sync(0xffffffffu, mt0, 2));
        mt1 = fmaxf(mt1, __shfl_xor_sync(0xffffffffu, mt1, 1));
        mt1 = fmaxf(mt1, __shfl_xor_sync(0xffffffffu, mt1, 2));
        float mn0 = fmaxf(mrow[0], mt0), mn1 = fmaxf(mrow[1], mt1);
        float sc0 = exp2f(mrow[0] - mn0), sc1 = exp2f(mrow[1] - mn1);
        mrow[0] = mn0; mrow[1] = mn1;
        #pragma unroll
        for (int nt = 0; nt < 8; nt++) {
            oacc[nt][0] *= sc0; oacc[nt][1] *= sc0;
            oacc[nt][2] *= sc1; oacc[nt][3] *= sc1;
        }

        // ---- interleaved exp2 + PV mma; l kept per-lane (deferred reduce) ----
        float lt0 = 0.f, lt1 = 0.f;
        #pragma unroll
        for (int kk = 0; kk < 4; kk++) {
            float p00 = exp2f(sacc[2*kk][0]   - mn0);
            float p01 = exp2f(sacc[2*kk][1]   - mn0);
            float p02 = exp2f(sacc[2*kk][2]   - mn1);
            float p03 = exp2f(sacc[2*kk][3]   - mn1);
            float p10 = exp2f(sacc[2*kk+1][0] - mn0);
            float p11 = exp2f(sacc[2*kk+1][1] - mn0);
            float p12 = exp2f(sacc[2*kk+1][2] - mn1);
            float p13 = exp2f(sacc[2*kk+1][3] - mn1);
            lt0 += (p00 + p01) + (p10 + p11);
            lt1 += (p02 + p03) + (p12 + p13);
            uint32_t pa[4];
            pa[0] = packh2(p00, p01);
            pa[1] = packh2(p02, p03);
            pa[2] = packh2(p10, p11);
            pa[3] = packh2(p12, p13);
            uint32_t rowb = vbase + vtOff + kk * (16 * ALD);
            #pragma unroll
            for (int p = 0; p < 4; p++) {
                uint32_t t4[4];
                ldm_x4_t(t4, rowb + p * 32);
                uint32_t b0[2] = {t4[0], t4[1]}, b1[2] = {t4[2], t4[3]};
                mma_f16(oacc[2*p],   pa, b0);
                mma_f16(oacc[2*p+1], pa, b1);
            }
        }
        // sc is row-uniform across the 4 lanes -> linear recurrence distributes;
        // 4-lane reduce deferred to after the loop.
        lpart[0] = lpart[0] * sc0 + lt0;
        lpart[1] = lpart[1] * sc1 + lt1;
    }

    // ---- final 4-lane l reduction + epilogue ----
    float l0 = lpart[0], l1 = lpart[1];
    l0 += __shfl_xor_sync(0xffffffffu, l0, 1);
    l0 += __shfl_xor_sync(0xffffffffu, l0, 2);
    l1 += __shfl_xor_sync(0xffffffffu, l1, 1);
    l1 += __shfl_xor_sync(0xffffffffu, l1, 2);
    float inv0 = 1.0f / l0, inv1 = 1.0f / l1;
    int g = lane >> 2, tq = lane & 3;
    int row0 = qt * 128 + wm * 16 + g;
    #pragma unroll
    for (int nt = 0; nt < 8; nt++) {
        int d = h * DH + nt * 8 + tq * 2;
        *(uint32_t*)(O + (size_t)(b * SEQL + row0) * DM + d) =
            packh2(oacc[nt][0] * inv0, oacc[nt][1] * inv0);
        *(uint32_t*)(O + (size_t)(b * SEQL + row0 + 8) * DM + d) =
            packh2(oacc[nt][2] * inv1, oacc[nt][3] * inv1);
    }
}

// ---------------- launch ----------------
extern "C" void kernel_launch(void* const* d_in, const int* in_sizes, int n_in,
                              void* d_out, int out_size)
{
    const float* x   = (const float*)d_in[0];
    const float* wq  = (const float*)d_in[1];
    const float* wk  = (const float*)d_in[2];
    const float* wv  = (const float*)d_in[3];
    const float* wo  = (const float*)d_in[4];
    const float* w1  = (const float*)d_in[5];
    const float* b1  = (const float*)d_in[6];
    const float* w2  = (const float*)d_in[7];
    const float* b2  = (const float*)d_in[8];
    const float* g1  = (const float*)d_in[9];
    const float* be1 = (const float*)d_in[10];
    const float* g2  = (const float*)d_in[11];
    const float* be2 = (const float*)d_in[12];
    float* out = (float*)d_out;

    float* x1;
    cudaGetSymbolAddress((void**)&x1, g_x1);
    __half *xnh, *qkv16, *attn16, *hid16;
    __half *wqkv16, *wo16, *w116, *w216;
    cudaGetSymbolAddress((void**)&xnh,    g_xnh);
    cudaGetSymbolAddress((void**)&qkv16,  g_qkv16);
    cudaGetSymbolAddress((void**)&attn16, g_attn16);
    cudaGetSymbolAddress((void**)&hid16,  g_hid16);
    cudaGetSymbolAddress((void**)&wqkv16, g_wqkv16);
    cudaGetSymbolAddress((void**)&wo16,   g_wo16);
    cudaGetSymbolAddress((void**)&w116,   g_w116);
    cudaGetSymbolAddress((void**)&w216,   g_w216);
    __half* q16 = qkv16;
    __half* k16 = qkv16 + (size_t)TOK * DM;
    __half* v16 = qkv16 + 2 * (size_t)TOK * DM;

    cudaFuncSetAttribute(attn_tc_kernel, cudaFuncAttributeMaxDynamicSharedMemorySize,
                         ATT_SMEM);
    cudaFuncSetAttribute(tc_gemm_kernel<false, false, false, true, true>,
                         cudaFuncAttributeMaxDynamicSharedMemorySize, GEMM_SMEM);
    cudaFuncSetAttribute(tc_gemm_kernel<true, true, false, true, false>,
                         cudaFuncAttributeMaxDynamicSharedMemorySize, GEMM_SMEM);
    cudaFuncSetAttribute(tc_gemm128_kernel<false, true>,
                         cudaFuncAttributeMaxDynamicSharedMemorySize, GEMM128_SMEM);
    cudaFuncSetAttribute(tc_gemm128_kernel<true, true>,
                         cudaFuncAttributeMaxDynamicSharedMemorySize, GEMM128_SMEM);

    // fused weight prep + LN1 (single launch)
    wprep_kernel<<<14336, dim3(32, 8)>>>(wq, wk, wv, wo, w1, w2,
                                         wqkv16, wo16, w116, w216,
                                         x, g1, be1, xnh);

    // fused QKV projection (N=3072) -> q|k|v fp16 (q pre-scaled)
    tc_gemm_kernel<false, false, false, true, true>
        <<<dim3(3 * DM / 128, TOK / 256), 256, GEMM_SMEM>>>(
        xnh, wqkv16, nullptr, nullptr, nullptr, qkv16, TOK, 3 * DM, DM);

    // tensor-core attention -> fp16
    attn_tc_kernel<<<dim3(SEQL / 128, NH, NB), 256, ATT_SMEM>>>(q16, k16, v16, attn16);

    // O projection + residual(x) -> x1 (fp32) — 128x128 tiles, grid 8x32=256
    tc_gemm128_kernel<false, true>
        <<<dim3(DM / 128, TOK / 128), 256, GEMM128_SMEM>>>(
        attn16, wo16, nullptr, x, x1, TOK, DM, DM);

    // LN2 -> fp16
    ln_kernel<<<TOK, 128>>>(x1, g2, be2, xnh);

    // FFN1: relu(xn @ w1 + b1) -> fp16 hid
    tc_gemm_kernel<true, true, false, true, false>
        <<<dim3(HID / 128, TOK / 256), 256, GEMM_SMEM>>>(
        xnh, w116, b1, nullptr, nullptr, hid16, TOK, HID, DM);

    // FFN2: hid @ w2 + b2 + x1 -> out (fp32) — 128x128 tiles, grid 8x32=256
    tc_gemm128_kernel<true, true>
        <<<dim3(DM / 128, TOK / 128), 256, GEMM128_SMEM>>>(
        hid16, w216, b2, x1, out, TOK, DM, HID);
}

// round 16
// speedup vs baseline: 1.0398x; 1.0226x over previous
#include <cuda_runtime.h>
#include <cuda_fp16.h>
#include <math.h>
#include <stdint.h>

#define TOK   4096   // B*S tokens
#define DM    1024
#define HID   4096
#define SEQL  2048
#define NB    2
#define NH    16
#define DH    64

// ---------------- scratch (allocation-free: __device__ globals) ----------------
__device__ float g_x1[TOK * DM];                         // residual after attention
__device__ __align__(256) __half g_xnh[TOK * DM];        // LN output, fp16
__device__ __align__(256) __half g_qkv16[3 * TOK * DM];  // fused q|k|v (q pre-scaled)
__device__ __align__(256) __half g_attn16[TOK * DM];
__device__ __align__(256) __half g_hid16[TOK * HID];
// weights in NATURAL [K,N] layout, fp16 (no transpose needed)
__device__ __align__(256) __half g_wqkv16[DM * 3 * DM];  // [1024][3072] wq|wk|wv cols
__device__ __align__(256) __half g_wo16[DM * DM];        // [1024][1024]
__device__ __align__(256) __half g_w116[DM * HID];       // [1024][4096]
__device__ __align__(256) __half g_w216[HID * DM];       // [4096][1024]

#define SC_LOG2E 0.1803368801111f   // 0.125 * log2(e), folded into Q

// ---------------- base-target PTX helpers ----------------
__device__ __forceinline__ uint32_t smem_u32(const void* p) {
    uint32_t a;
    asm("{ .reg .u64 t; cvta.to.shared.u64 t, %1; cvt.u32.u64 %0, t; }"
        : "=r"(a) : "l"(p));
    return a;
}
__device__ __forceinline__ void cpa16(uint32_t s, const void* g) {
    asm volatile("cp.async.cg.shared.global [%0], [%1], 16;" :: "r"(s), "l"(g));
}
#define CP_COMMIT() asm volatile("cp.async.commit_group;" ::: "memory")
#define CP_WAIT(n)  asm volatile("cp.async.wait_group %0;" :: "n"(n) : "memory")

__device__ __forceinline__ void ldm_x4(uint32_t* r, uint32_t addr) {
    asm volatile("ldmatrix.sync.aligned.m8n8.x4.shared.b16 {%0,%1,%2,%3}, [%4];"
                 : "=r"(r[0]), "=r"(r[1]), "=r"(r[2]), "=r"(r[3]) : "r"(addr));
}
__device__ __forceinline__ void ldm_x4_t(uint32_t* r, uint32_t addr) {
    asm volatile("ldmatrix.sync.aligned.m8n8.x4.trans.shared.b16 {%0,%1,%2,%3}, [%4];"
                 : "=r"(r[0]), "=r"(r[1]), "=r"(r[2]), "=r"(r[3]) : "r"(addr));
}
__device__ __forceinline__ void mma_f16(float* d, const uint32_t* a, const uint32_t* b) {
    asm volatile(
        "mma.sync.aligned.m16n8k16.row.col.f32.f16.f16.f32 "
        "{%0,%1,%2,%3}, {%4,%5,%6,%7}, {%8,%9}, {%0,%1,%2,%3};"
        : "+f"(d[0]), "+f"(d[1]), "+f"(d[2]), "+f"(d[3])
        : "r"(a[0]), "r"(a[1]), "r"(a[2]), "r"(a[3]), "r"(b[0]), "r"(b[1]));
}
__device__ __forceinline__ uint32_t packh2(float lo, float hi) {
    __half2 t = __floats2half2_rn(lo, hi);
    return *(uint32_t*)&t;
}

// ---------------- LayerNorm helper (128 threads per token) ----------------
__device__ __forceinline__ void ln_token(const float* __restrict__ xrow,
                                         const float* __restrict__ gamma,
                                         const float* __restrict__ beta,
                                         __half* __restrict__ orow,
                                         int sub, float* smred)
{
    const float4* xr = (const float4*)xrow;
    float4 v0 = xr[sub];
    float4 v1 = xr[sub + 128];
    float s  = v0.x + v0.y + v0.z + v0.w + v1.x + v1.y + v1.z + v1.w;
    float ss = v0.x*v0.x + v0.y*v0.y + v0.z*v0.z + v0.w*v0.w
             + v1.x*v1.x + v1.y*v1.y + v1.z*v1.z + v1.w*v1.w;
    #pragma unroll
    for (int o = 16; o; o >>= 1) {
        s  += __shfl_xor_sync(0xffffffffu, s,  o);
        ss += __shfl_xor_sync(0xffffffffu, ss, o);
    }
    int w = sub >> 5, ln = sub & 31;
    if (ln == 0) { smred[w] = s; smred[4 + w] = ss; }
    __syncthreads();
    s  = smred[0] + smred[1] + smred[2] + smred[3];
    ss = smred[4] + smred[5] + smred[6] + smred[7];
    float mu   = s * (1.0f / DM);
    float var  = ss * (1.0f / DM) - mu * mu;
    float rstd = rsqrtf(var + 1e-5f);

    const float4* gr = (const float4*)gamma;
    const float4* br = (const float4*)beta;
    #pragma unroll
    for (int u = 0; u < 2; u++) {
        int i = sub + u * 128;
        float4 xv = xr[i], gv = gr[i], bv = br[i];
        float rx = (xv.x - mu) * rstd * gv.x + bv.x;
        float ry = (xv.y - mu) * rstd * gv.y + bv.y;
        float rz = (xv.z - mu) * rstd * gv.z + bv.z;
        float rw = (xv.w - mu) * rstd * gv.w + bv.w;
        uint2 pk;
        pk.x = packh2(rx, ry);
        pk.y = packh2(rz, rw);
        *(uint2*)(orow + i * 4) = pk;
    }
}

// ---------------- standalone LN (for LN2) ----------------
__global__ void ln_kernel(const float* __restrict__ x,
                          const float* __restrict__ gamma,
                          const float* __restrict__ beta,
                          __half* __restrict__ out)
{
    __shared__ float smred[8];
    int t = blockIdx.x;
    ln_token(x + (size_t)t * DM, gamma, beta, out + (size_t)t * DM,
             threadIdx.x, smred);
}

// ------- fused prep: streaming fp32->fp16 weight converts + LN1, one launch ----
// blocks [0,3072): wq|wk|wv interleave into [1024][3072]
// blocks [3072,4096): wo; [4096,8192): w1; [8192,12288): w2 (identity convert)
// blocks [12288,14336): LN1, 2 tokens each. 256 threads, 4 elems/thread.
__global__ void wprep_kernel(const float* __restrict__ wq, const float* __restrict__ wk,
                             const float* __restrict__ wv, const float* __restrict__ wo,
                             const float* __restrict__ w1, const float* __restrict__ w2,
                             __half* __restrict__ owqkv, __half* __restrict__ owo,
                             __half* __restrict__ ow1,   __half* __restrict__ ow2,
                             const float* __restrict__ x,
                             const float* __restrict__ g1, const float* __restrict__ be1,
                             __half* __restrict__ oln)
{
    __shared__ float smred[2][8];
    int bid = blockIdx.x;
    int tid = threadIdx.x;

    if (bid >= 12288) {
        int tok = (bid - 12288) * 2 + (tid >> 7);
        ln_token(x + (size_t)tok * DM, g1, be1, oln + (size_t)tok * DM,
                 tid & 127, smred[tid >> 7]);
        return;
    }

    if (bid < 3072) {
        int which = bid >> 10;
        const float* src = (which == 0) ? wq : ((which == 1) ? wk : wv);
        int e = ((bid & 1023) * 256 + tid) * 4;      // element within 1M
        int k = e >> 10, n = e & 1023;
        float4 v = *(const float4*)(src + e);
        uint2 pk;
        pk.x = packh2(v.x, v.y);
        pk.y = packh2(v.z, v.w);
        *(uint2*)(owqkv + (size_t)k * 3072 + which * 1024 + n) = pk;
    } else {
        const float* src; __half* dst; int base;
        if (bid < 4096)      { src = wo; dst = owo; base = bid - 3072; }
        else if (bid < 8192) { src = w1; dst = ow1; base = bid - 4096; }
        else                 { src = w2; dst = ow2; base = bid - 8192; }
        int e = (base * 256 + tid) * 4;
        float4 v = *(const float4*)(src + e);
        uint2 pk;
        pk.x = packh2(v.x, v.y);
        pk.y = packh2(v.z, v.w);
        *(uint2*)(dst + e) = pk;
    }
}

// ---------------- mma.sync fp16 GEMM, 256x128 CTA tile, 4-stage ring ----------
// A [M,K] row-major; B [K,N] natural layout, B-frags via ldmatrix.trans.
#define GLDA      144
#define GLDB      272                      // 128 n halfs (256B) + 16 pad
#define GA_BYTES  (256 * GLDA)             // 36864
#define GB_BYTES  (64 * GLDB)              // 17408
#define GSTAGE    (GA_BYTES + GB_BYTES)    // 54272
#define GEMM_SMEM (4 * GSTAGE)             // 217088

template<bool BIAS, bool RELU, bool RES, bool OUTH, bool QKVOUT>
__global__ void __launch_bounds__(256) tc_gemm_kernel(
    const __half* __restrict__ A, const __half* __restrict__ B,
    const float* __restrict__ bias, const float* __restrict__ Res,
    float* __restrict__ Cf, __half* __restrict__ Ch, int M, int N, int K)
{
    extern __shared__ char smem[];
    const uint32_t sb = smem_u32(smem);
    int tid = threadIdx.x;
    int wid = tid >> 5, lane = tid & 31;
    int wm = wid & 3, wn = wid >> 2;
    int m0 = blockIdx.y * 256, n0 = blockIdx.x * 128;

    float acc[4][8][4];
    #pragma unroll
    for (int i = 0; i < 4; i++)
        #pragma unroll
        for (int j = 0; j < 8; j++)
            #pragma unroll
            for (int r = 0; r < 4; r++) acc[i][j][r] = 0.f;

    int nc = K >> 6;

    auto load_chunk = [&](int c, int st) {
        int kc = c << 6;
        uint32_t base = sb + st * GSTAGE;
        #pragma unroll
        for (int i = 0; i < 12; i++) {
            int slot = tid + (i << 8);
            if (slot < 2048) {                 // A: 256 rows x 8 chunks
                int r = slot >> 3, ch = slot & 7;
                cpa16(base + r * GLDA + ch * 16,
                      A + (size_t)(m0 + r) * K + kc + ch * 8);
            } else {                           // B: 64 k-rows x 16 chunks (128 n)
                int s2 = slot - 2048;
                int r = s2 >> 4, ch = s2 & 15;
                cpa16(base + GA_BYTES + r * GLDB + ch * 16,
                      B + (size_t)(kc + r) * N + n0 + ch * 8);
            }
        }
        CP_COMMIT();
    };

    load_chunk(0, 0);
    load_chunk(1, 1);
    load_chunk(2, 2);

    uint32_t aOff = (uint32_t)((wm * 64 + (lane & 15)) * GLDA + (lane >> 4) * 16);
    uint32_t bOff = (uint32_t)((lane & 15) * GLDB + (lane >> 4) * 16 + wn * 128);

    for (int c = 0; c < nc; c++) {
        int st = c & 3;
        CP_WAIT(2);
        __syncthreads();
        if (c + 3 < nc) load_chunk(c + 3, (c + 3) & 3);
        else            CP_COMMIT();
        uint32_t base = sb + st * GSTAGE;
        #pragma unroll
        for (int ks = 0; ks < 4; ks++) {
            uint32_t af[4][4], bf[8][2];
            #pragma unroll
            for (int mt = 0; mt < 4; mt++)
                ldm_x4(af[mt], base + aOff + mt * (16 * GLDA) + ks * 32);
            uint32_t brow = base + GA_BYTES + bOff + ks * (16 * GLDB);
            #pragma unroll
            for (int p = 0; p < 4; p++) {
                uint32_t t4[4];
                ldm_x4_t(t4, brow + p * 32);
                bf[2*p][0] = t4[0]; bf[2*p][1] = t4[1];
                bf[2*p+1][0] = t4[2]; bf[2*p+1][1] = t4[3];
            }
            #pragma unroll
            for (int mt = 0; mt < 4; mt++)
                #pragma unroll
                for (int nt = 0; nt < 8; nt++)
                    mma_f16(acc[mt][nt], af[mt], bf[nt]);
        }
    }

    int g = lane >> 2, tq = lane & 3;
    #pragma unroll
    for (int mt = 0; mt < 4; mt++) {
        int mbase = m0 + wm * 64 + mt * 16 + g;
        #pragma unroll
        for (int nt = 0; nt < 8; nt++) {
            int n = n0 + wn * 64 + nt * 8 + tq * 2;
            float2 v0 = make_float2(acc[mt][nt][0], acc[mt][nt][1]);
            float2 v1 = make_float2(acc[mt][nt][2], acc[mt][nt][3]);
            if (BIAS) {
                float2 bb = *(const float2*)(bias + n);
                v0.x += bb.x; v0.y += bb.y; v1.x += bb.x; v1.y += bb.y;
            }
            if (RELU) {
                v0.x = fmaxf(v0.x, 0.f); v0.y = fmaxf(v0.y, 0.f);
                v1.x = fmaxf(v1.x, 0.f); v1.y = fmaxf(v1.y, 0.f);
            }
            if (RES) {
                float2 q0 = *(const float2*)(Res + (size_t)mbase * N + n);
                float2 q1 = *(const float2*)(Res + (size_t)(mbase + 8) * N + n);
                v0.x += q0.x; v0.y += q0.y; v1.x += q1.x; v1.y += q1.y;
            }
            if (QKVOUT) {
                int which = n >> 10, nn = n & 1023;
                if (which == 0) {
                    v0.x *= SC_LOG2E; v0.y *= SC_LOG2E;
                    v1.x *= SC_LOG2E; v1.y *= SC_LOG2E;
                }
                __half* dst = Ch + (size_t)which * (TOK * DM) + (size_t)mbase * DM + nn;
                *(uint32_t*)dst                    = packh2(v0.x, v0.y);
                *(uint32_t*)(dst + (size_t)8 * DM) = packh2(v1.x, v1.y);
            } else if (OUTH) {
                *(uint32_t*)(Ch + (size_t)mbase * N + n)       = packh2(v0.x, v0.y);
                *(uint32_t*)(Ch + (size_t)(mbase + 8) * N + n) = packh2(v1.x, v1.y);
            } else {
                *(float2*)(Cf + (size_t)mbase * N + n) = v0;
                *(float2*)(Cf + (size_t)(mbase + 8) * N + n) = v1;
            }
        }
    }
}

// ---------------- 128x128-tile GEMM for N=1024 GEMMs (O-proj, FFN2) -----------
#define H_A_BYTES (128 * GLDA)             // 18432
#define H_STAGE   (H_A_BYTES + GB_BYTES)   // 35840
#define GEMM128_SMEM (3 * H_STAGE)         // 107520

template<bool BIAS, bool RES>
__global__ void __launch_bounds__(256) tc_gemm128_kernel(
    const __half* __restrict__ A, const __half* __restrict__ B,
    const float* __restrict__ bias, const float* __restrict__ Res,
    float* __restrict__ Cf, int M, int N, int K)
{
    extern __shared__ char smem[];
    const uint32_t sb = smem_u32(smem);
    int tid = threadIdx.x;
    int wid = tid >> 5, lane = tid & 31;
    int wm = wid & 1, wn = wid >> 1;
    int m0 = blockIdx.y * 128, n0 = blockIdx.x * 128;

    float acc[4][4][4];
    #pragma unroll
    for (int i = 0; i < 4; i++)
        #pragma unroll
        for (int j = 0; j < 4; j++)
            #pragma unroll
            for (int r = 0; r < 4; r++) acc[i][j][r] = 0.f;

    int nc = K >> 6;

    auto load_chunk = [&](int c, int st) {
        int kc = c << 6;
        uint32_t base = sb + st * H_STAGE;
        #pragma unroll
        for (int i = 0; i < 8; i++) {
            int slot = tid + (i << 8);
            if (slot < 1024) {                 // A: 128 rows x 8 chunks
                int r = slot >> 3, ch = slot & 7;
                cpa16(base + r * GLDA + ch * 16,
                      A + (size_t)(m0 + r) * K + kc + ch * 8);
            } else {                           // B: 64 k-rows x 16 chunks
                int s2 = slot - 1024;
                int r = s2 >> 4, ch = s2 & 15;
                cpa16(base + H_A_BYTES + r * GLDB + ch * 16,
                      B + (size_t)(kc + r) * N + n0 + ch * 8);
            }
        }
        CP_COMMIT();
    };

    load_chunk(0, 0);
    load_chunk(1, 1);

    uint32_t aOff = (uint32_t)((wm * 64 + (lane & 15)) * GLDA + (lane >> 4) * 16);
    uint32_t bOff = (uint32_t)((lane & 15) * GLDB + (lane >> 4) * 16 + wn * 64);

    for (int c = 0; c < nc; c++) {
        int st = c % 3;
        CP_WAIT(1);
        __syncthreads();
        if (c + 2 < nc) load_chunk(c + 2, (c + 2) % 3);
        else            CP_COMMIT();
        uint32_t base = sb + st * H_STAGE;
        #pragma unroll
        for (int ks = 0; ks < 4; ks++) {
            uint32_t af[4][4], bf[4][2];
            #pragma unroll
            for (int mt = 0; mt < 4; mt++)
                ldm_x4(af[mt], base + aOff + mt * (16 * GLDA) + ks * 32);
            uint32_t brow = base + H_A_BYTES + bOff + ks * (16 * GLDB);
            #pragma unroll
            for (int p = 0; p < 2; p++) {
                uint32_t t4[4];
                ldm_x4_t(t4, brow + p * 32);
                bf[2*p][0] = t4[0]; bf[2*p][1] = t4[1];
                bf[2*p+1][0] = t4[2]; bf[2*p+1][1] = t4[3];
            }
            #pragma unroll
            for (int mt = 0; mt < 4; mt++)
                #pragma unroll
                for (int nt = 0; nt < 4; nt++)
                    mma_f16(acc[mt][nt], af[mt], bf[nt]);
        }
    }

    int g = lane >> 2, tq = lane & 3;
    #pragma unroll
    for (int mt = 0; mt < 4; mt++) {
        int mbase = m0 + wm * 64 + mt * 16 + g;
        #pragma unroll
        for (int nt = 0; nt < 4; nt++) {
            int n = n0 + wn * 32 + nt * 8 + tq * 2;
            float2 v0 = make_float2(acc[mt][nt][0], acc[mt][nt][1]);
            float2 v1 = make_float2(acc[mt][nt][2], acc[mt][nt][3]);
            if (BIAS) {
                float2 bb = *(const float2*)(bias + n);
                v0.x += bb.x; v0.y += bb.y; v1.x += bb.x; v1.y += bb.y;
            }
            if (RES) {
                float2 q0 = *(const float2*)(Res + (size_t)mbase * N + n);
                float2 q1 = *(const float2*)(Res + (size_t)(mbase + 8) * N + n);
                v0.x += q0.x; v0.y += q0.y; v1.x += q1.x; v1.y += q1.y;
            }
            *(float2*)(Cf + (size_t)mbase * N + n) = v0;
            *(float2*)(Cf + (size_t)(mbase + 8) * N + n) = v1;
        }
    }
}

// ---------------- tensor-core flash attention (fp16, base-2 softmax) ----------
// 128 queries, 256 threads, 4 KV stages, one sync per tile, deferred l-reduce.
#define ALD  144
#define ATB  (64 * ALD)
#define QTB  (128 * ALD)
#define ASTG (2 * ATB)              // K, V per stage
#define ATT_SMEM (QTB + 4 * ASTG)   // 92160

__global__ void __launch_bounds__(256) attn_tc_kernel(
    const __half* __restrict__ Q, const __half* __restrict__ K,
    const __half* __restrict__ V, __half* __restrict__ O)
{
    extern __shared__ char smc[];
    const uint32_t sb = smem_u32(smc);
    int qt = (int)gridDim.x - 1 - (int)blockIdx.x;
    int h = blockIdx.y, b = blockIdx.z;
    int tid = threadIdx.x;
    int wm = tid >> 5, lane = tid & 31;

    auto load_kv = [&](int t, int st) {
        uint32_t base = sb + QTB + st * ASTG;
        #pragma unroll
        for (int i = 0; i < 2; i++) {
            int slot = tid * 2 + i;
            int r = slot >> 3, c = slot & 7;
            size_t gk = (size_t)(b * SEQL + t * 64 + r) * DM + h * DH + c * 8;
            uint32_t so = (uint32_t)(r * ALD + c * 16);
            cpa16(base + so,       K + gk);
            cpa16(base + ATB + so, V + gk);
        }
    };

    int ntile = 2 * qt + 2;

    #pragma unroll
    for (int i = 0; i < 4; i++) {
        int slot = tid * 4 + i;
        int r = slot >> 3, c = slot & 7;
        size_t gq = (size_t)(b * SEQL + qt * 128 + r) * DM + h * DH + c * 8;
        cpa16(sb + (uint32_t)(r * ALD + c * 16), Q + gq);
    }
    load_kv(0, 0);
    CP_COMMIT();
    if (ntile > 1) load_kv(1, 1);
    CP_COMMIT();
    if (ntile > 2) load_kv(2, 2);
    CP_COMMIT();

    float oacc[8][4];
    #pragma unroll
    for (int nt = 0; nt < 8; nt++)
        #pragma unroll
        for (int j = 0; j < 4; j++) oacc[nt][j] = 0.f;
    float mrow[2] = {-INFINITY, -INFINITY};
    float lpart[2] = {0.f, 0.f};

    uint32_t aOff = (uint32_t)((wm * 16 + (lane & 15)) * ALD + (lane >> 4) * 16);
    int bm = lane >> 3, brr = lane & 7;
    uint32_t bOff = (uint32_t)((((bm & 2) ? 8 : 0) + brr) * ALD + ((bm & 1) ? 16 : 0));
    uint32_t vtOff = (uint32_t)((lane & 15) * ALD + (lane >> 4) * 16);

    for (int t = 0; t < ntile; t++) {
        int st = t & 3;
        CP_WAIT(2);
        __syncthreads();
        if (t + 3 < ntile) { load_kv(t + 3, (t + 3) & 3); CP_COMMIT(); }
        else               { CP_COMMIT(); }

        uint32_t kbase = sb + QTB + st * ASTG;
        uint32_t vbase = kbase + ATB;

        float sacc[8][4];
        #pragma unroll
        for (int nt = 0; nt < 8; nt++)
            #pragma unroll
            for (int j = 0; j < 4; j++) sacc[nt][j] = 0.f;

        #pragma unroll
        for (int kt = 0; kt < 4; kt++) {
            uint32_t kb = kt * 32;
            uint32_t a4[4];
            ldm_x4(a4, sb + aOff + kb);
            #pragma unroll
            for (int p = 0; p < 4; p++) {
                uint32_t t4[4];
                ldm_x4(t4, kbase + bOff + p * (16 * ALD) + kb);
                uint32_t b0[2] = {t4[0], t4[1]}, b1[2] = {t4[2], t4[3]};
                mma_f16(sacc[2*p],   a4, b0);
                mma_f16(sacc[2*p+1], a4, b1);
            }
        }

        int g = lane >> 2, colb = (lane & 3) * 2;
        if (t >= 2 * qt) {
            #pragma unroll
            for (int nt = 0; nt < 8; nt++)
                #pragma unroll
                for (int j = 0; j < 4; j++) {
                    int col = t * 64 + nt * 8 + colb + (j & 1);
                    int qr  = qt * 128 + wm * 16 + g + ((j >= 2) ? 8 : 0);
                    if (col > qr) sacc[nt][j] = -1e30f;
                }
        }

        float mt0 = -INFINITY, mt1 = -INFINITY;
        #pragma unroll
        for (int nt = 0; nt < 8; nt++) {
            mt0 = fmaxf(mt0, fmaxf(sacc[nt][0], sacc[nt][1]));
            mt1 = fmaxf(mt1, fmaxf(sacc[nt][2], sacc[nt][3]));
        }
        mt0 = fmaxf(mt0, __shfl_xor_sync(0xffffffffu, mt0, 1));
        mt0 = fmaxf(mt0, __shfl_xor_sync(0xffffffffu, mt0, 2));
        mt1 = fmaxf(mt1, __shfl_xor_sync(0xffffffffu, mt1, 1));
        mt1 = fmaxf(mt1, __shfl_xor_sync(0xffffffffu, mt1, 2));
        float mn0 = fmaxf(mrow[0], mt0), mn1 = fmaxf(mrow[1], mt1);
        float sc0 = exp2f(mrow[0] - mn0), sc1 = exp2f(mrow[1] - mn1);
        mrow[0] = mn0; mrow[1] = mn1;
        #pragma unroll
        for (int nt = 0; nt < 8; nt++) {
            oacc[nt][0] *= sc0; oacc[nt][1] *= sc0;
            oacc[nt][2] *= sc1; oacc[nt][3] *= sc1;
        }

        float lt0 = 0.f, lt1 = 0.f;
        #pragma unroll
        for (int kk = 0; kk < 4; kk++) {
            float p00 = exp2f(sacc[2*kk][0]   - mn0);
            float p01 = exp2f(sacc[2*kk][1]   - mn0);
            float p02 = exp2f(sacc[2*kk][2]   - mn1);
            float p03 = exp2f(sacc[2*kk][3]   - mn1);
            float p10 = exp2f(sacc[2*kk+1][0] - mn0);
            float p11 = exp2f(sacc[2*kk+1][1] - mn0);
            float p12 = exp2f(sacc[2*kk+1][2] - mn1);
            float p13 = exp2f(sacc[2*kk+1][3] - mn1);
            lt0 += (p00 + p01) + (p10 + p11);
            lt1 += (p02 + p03) + (p12 + p13);
            uint32_t pa[4];
            pa[0] = packh2(p00, p01);
            pa[1] = packh2(p02, p03);
            pa[2] = packh2(p10, p11);
            pa[3] = packh2(p12, p13);
            uint32_t rowb = vbase + vtOff + kk * (16 * ALD);
            #pragma unroll
            for (int p = 0; p < 4; p++) {
                uint32_t t4[4];
                ldm_x4_t(t4, rowb + p * 32);
                uint32_t b0[2] = {t4[0], t4[1]}, b1[2] = {t4[2], t4[3]};
                mma_f16(oacc[2*p],   pa, b0);
                mma_f16(oacc[2*p+1], pa, b1);
            }
        }
        lpart[0] = lpart[0] * sc0 + lt0;
        lpart[1] = lpart[1] * sc1 + lt1;
    }

    float l0 = lpart[0], l1 = lpart[1];
    l0 += __shfl_xor_sync(0xffffffffu, l0, 1);
    l0 += __shfl_xor_sync(0xffffffffu, l0, 2);
    l1 += __shfl_xor_sync(0xffffffffu, l1, 1);
    l1 += __shfl_xor_sync(0xffffffffu, l1, 2);
    float inv0 = 1.0f / l0, inv1 = 1.0f / l1;
    int g = lane >> 2, tq = lane & 3;
    int row0 = qt * 128 + wm * 16 + g;
    #pragma unroll
    for (int nt = 0; nt < 8; nt++) {
        int d = h * DH + nt * 8 + tq * 2;
        *(uint32_t*)(O + (size_t)(b * SEQL + row0) * DM + d) =
            packh2(oacc[nt][0] * inv0, oacc[nt][1] * inv0);
        *(uint32_t*)(O + (size_t)(b * SEQL + row0 + 8) * DM + d) =
            packh2(oacc[nt][2] * inv1, oacc[nt][3] * inv1);
    }
}

// ---------------- launch ----------------
extern "C" void kernel_launch(void* const* d_in, const int* in_sizes, int n_in,
                              void* d_out, int out_size)
{
    const float* x   = (const float*)d_in[0];
    const float* wq  = (const float*)d_in[1];
    const float* wk  = (const float*)d_in[2];
    const float* wv  = (const float*)d_in[3];
    const float* wo  = (const float*)d_in[4];
    const float* w1  = (const float*)d_in[5];
    const float* b1  = (const float*)d_in[6];
    const float* w2  = (const float*)d_in[7];
    const float* b2  = (const float*)d_in[8];
    const float* g1  = (const float*)d_in[9];
    const float* be1 = (const float*)d_in[10];
    const float* g2  = (const float*)d_in[11];
    const float* be2 = (const float*)d_in[12];
    float* out = (float*)d_out;

    float* x1;
    cudaGetSymbolAddress((void**)&x1, g_x1);
    __half *xnh, *qkv16, *attn16, *hid16;
    __half *wqkv16, *wo16, *w116, *w216;
    cudaGetSymbolAddress((void**)&xnh,    g_xnh);
    cudaGetSymbolAddress((void**)&qkv16,  g_qkv16);
    cudaGetSymbolAddress((void**)&attn16, g_attn16);
    cudaGetSymbolAddress((void**)&hid16,  g_hid16);
    cudaGetSymbolAddress((void**)&wqkv16, g_wqkv16);
    cudaGetSymbolAddress((void**)&wo16,   g_wo16);
    cudaGetSymbolAddress((void**)&w116,   g_w116);
    cudaGetSymbolAddress((void**)&w216,   g_w216);
    __half* q16 = qkv16;
    __half* k16 = qkv16 + (size_t)TOK * DM;
    __half* v16 = qkv16 + 2 * (size_t)TOK * DM;

    cudaFuncSetAttribute(attn_tc_kernel, cudaFuncAttributeMaxDynamicSharedMemorySize,
                         ATT_SMEM);
    cudaFuncSetAttribute(tc_gemm_kernel<false, false, false, true, true>,
                         cudaFuncAttributeMaxDynamicSharedMemorySize, GEMM_SMEM);
    cudaFuncSetAttribute(tc_gemm_kernel<true, true, false, true, false>,
                         cudaFuncAttributeMaxDynamicSharedMemorySize, GEMM_SMEM);
    cudaFuncSetAttribute(tc_gemm128_kernel<false, true>,
                         cudaFuncAttributeMaxDynamicSharedMemorySize, GEMM128_SMEM);
    cudaFuncSetAttribute(tc_gemm128_kernel<true, true>,
                         cudaFuncAttributeMaxDynamicSharedMemorySize, GEMM128_SMEM);

    // fused streaming weight convert + LN1 (single launch)
    wprep_kernel<<<14336, 256>>>(wq, wk, wv, wo, w1, w2,
                                 wqkv16, wo16, w116, w216,
                                 x, g1, be1, xnh);

    // fused QKV projection (N=3072) -> q|k|v fp16 (q pre-scaled)
    tc_gemm_kernel<false, false, false, true, true>
        <<<dim3(3 * DM / 128, TOK / 256), 256, GEMM_SMEM>>>(
        xnh, wqkv16, nullptr, nullptr, nullptr, qkv16, TOK, 3 * DM, DM);

    // tensor-core attention -> fp16
    attn_tc_kernel<<<dim3(SEQL / 128, NH, NB), 256, ATT_SMEM>>>(q16, k16, v16, attn16);

    // O projection + residual(x) -> x1 (fp32) — 128x128 tiles, grid 8x32=256
    tc_gemm128_kernel<false, true>
        <<<dim3(DM / 128, TOK / 128), 256, GEMM128_SMEM>>>(
        attn16, wo16, nullptr, x, x1, TOK, DM, DM);

    // LN2 -> fp16
    ln_kernel<<<TOK, 128>>>(x1, g2, be2, xnh);

    // FFN1: relu(xn @ w1 + b1) -> fp16 hid
    tc_gemm_kernel<true, true, false, true, false>
        <<<dim3(HID / 128, TOK / 256), 256, GEMM_SMEM>>>(
        xnh, w116, b1, nullptr, nullptr, hid16, TOK, HID, DM);

    // FFN2: hid @ w2 + b2 + x1 -> out (fp32) — 128x128 tiles, grid 8x32=256
    tc_gemm128_kernel<true, true>
        <<<dim3(DM / 128, TOK / 128), 256, GEMM128_SMEM>>>(
        hid16, w216, b2, x1, out, TOK, DM, HID);
}